// round 3
// baseline (speedup 1.0000x reference)
#include <cuda_runtime.h>
#include <math.h>

#define BATCH  2
#define S_LEN  2048
#define HID_D  2048
#define NH     16
#define NKV    2
#define HD     128
#define QKV_N  ((NH + 2*NKV) * HD)   // 2560
#define NTOK   (BATCH * S_LEN)       // 4096
#define OUT_N  (NH * HD)             // 2048
#define SCALE  0.08838834764831843f  // 128^-0.5

// ---------------- scratch (device globals; no allocation allowed) ----------------
__device__ __align__(16) float g_qkv[(size_t)NTOK * QKV_N];    // 41.9 MB
__device__ __align__(16) float g_attn[(size_t)NTOK * OUT_N];   // 33.5 MB
__device__ __align__(16) float g_cs[(size_t)S_LEN * HD];       // [s][0..63]=cos, [64..127]=sin

// ---------------- RoPE cos/sin table (fp64 for angle accuracy) ----------------
__global__ void rope_table_kernel() {
    int idx = blockIdx.x * blockDim.x + threadIdx.x;
    if (idx >= S_LEN * 64) return;
    int s = idx >> 6, i = idx & 63;
    double inv = pow(1000000.0, -(double)i / 64.0);
    double ang = (double)s * inv;
    g_cs[s * HD + i]      = (float)cos(ang);
    g_cs[s * HD + 64 + i] = (float)sin(ang);
}

// ---------------- RoPE apply (q: 16 heads, k: 2 heads) ----------------
__global__ void rope_apply_kernel(const int* __restrict__ positions) {
    size_t idx = (size_t)blockIdx.x * blockDim.x + threadIdx.x;
    const size_t total = (size_t)NTOK * (NH + NKV) * 64;
    if (idx >= total) return;
    int i    = idx & 63;
    size_t r = idx >> 6;
    int head = (int)(r % (NH + NKV));
    int t    = (int)(r / (NH + NKV));
    int pos  = positions[t];
    float c  = g_cs[pos * HD + i];
    float sn = g_cs[pos * HD + 64 + i];
    int off  = (head < NH) ? head * HD : (NH * HD + (head - NH) * HD);
    float* p = g_qkv + (size_t)t * QKV_N + off;
    float x1 = p[i], x2 = p[i + 64];
    p[i]      = x1 * c - x2 * sn;
    p[i + 64] = x2 * c + x1 * sn;
}

// ---------------- SGEMM: C[M,N] = A[M,K] @ B[K,N] (+bias), 128x128x8 tiles ----------------
template <bool BIAS>
__global__ __launch_bounds__(256) void sgemm_kernel(
    const float* __restrict__ A, const float* __restrict__ B,
    const float* __restrict__ bias, float* __restrict__ C,
    int M, int N, int K)
{
    __shared__ float As[2][8][132];   // transposed: As[k][m], pad 132 -> conflict-free
    __shared__ float Bs[2][8][128];   // Bs[k][n]

    const int tid = threadIdx.x;
    const int tx = tid & 15, ty = tid >> 4;
    const int bm = blockIdx.y * 128, bn = blockIdx.x * 128;

    // global load mapping
    const int arow = tid >> 1, ac4 = (tid & 1) * 4;     // A tile: 128 rows x 8 cols
    const int brow = tid >> 5, bc4 = (tid & 31) * 4;    // B tile: 8 rows x 128 cols
    const float* Aptr = A + (size_t)(bm + arow) * K + ac4;
    const float* Bptr = B + (size_t)brow * N + bn + bc4;

    float acc[8][8];
#pragma unroll
    for (int i = 0; i < 8; i++)
#pragma unroll
        for (int j = 0; j < 8; j++) acc[i][j] = 0.0f;

    const int nk = K >> 3;
    float4 av = *(const float4*)Aptr;
    float4 bv = *(const float4*)Bptr;

    // store tile 0
    As[0][ac4 + 0][arow] = av.x; As[0][ac4 + 1][arow] = av.y;
    As[0][ac4 + 2][arow] = av.z; As[0][ac4 + 3][arow] = av.w;
    *(float4*)&Bs[0][brow][bc4] = bv;
    __syncthreads();

    int buf = 0;
    for (int kt = 0; kt < nk; kt++) {
        if (kt + 1 < nk) {
            av = *(const float4*)(Aptr + (kt + 1) * 8);
            bv = *(const float4*)(Bptr + (size_t)(kt + 1) * 8 * N);
        }
#pragma unroll
        for (int k = 0; k < 8; k++) {
            float4 a0 = *(const float4*)&As[buf][k][ty * 8];
            float4 a1 = *(const float4*)&As[buf][k][ty * 8 + 4];
            float4 b0 = *(const float4*)&Bs[buf][k][tx * 4];        // cols tx*4..+3
            float4 b1 = *(const float4*)&Bs[buf][k][64 + tx * 4];   // cols 64+tx*4..+3
            float ar[8] = {a0.x, a0.y, a0.z, a0.w, a1.x, a1.y, a1.z, a1.w};
            float br[8] = {b0.x, b0.y, b0.z, b0.w, b1.x, b1.y, b1.z, b1.w};
#pragma unroll
            for (int i = 0; i < 8; i++)
#pragma unroll
                for (int j = 0; j < 8; j++)
                    acc[i][j] = fmaf(ar[i], br[j], acc[i][j]);
        }
        if (kt + 1 < nk) {
            __syncthreads();
            int nb = buf ^ 1;
            As[nb][ac4 + 0][arow] = av.x; As[nb][ac4 + 1][arow] = av.y;
            As[nb][ac4 + 2][arow] = av.z; As[nb][ac4 + 3][arow] = av.w;
            *(float4*)&Bs[nb][brow][bc4] = bv;
            buf = nb;
            __syncthreads();
        }
    }

    float bias0[4] = {0, 0, 0, 0}, bias1[4] = {0, 0, 0, 0};
    if (BIAS) {
#pragma unroll
        for (int j = 0; j < 4; j++) {
            bias0[j] = bias[bn + tx * 4 + j];
            bias1[j] = bias[bn + 64 + tx * 4 + j];
        }
    }
#pragma unroll
    for (int i = 0; i < 8; i++) {
        int row = bm + ty * 8 + i;
        float4 c0, c1;
        c0.x = acc[i][0] + bias0[0]; c0.y = acc[i][1] + bias0[1];
        c0.z = acc[i][2] + bias0[2]; c0.w = acc[i][3] + bias0[3];
        c1.x = acc[i][4] + bias1[0]; c1.y = acc[i][5] + bias1[1];
        c1.z = acc[i][6] + bias1[2]; c1.w = acc[i][7] + bias1[3];
        *(float4*)&C[(size_t)row * N + bn + tx * 4]      = c0;
        *(float4*)&C[(size_t)row * N + bn + 64 + tx * 4] = c1;
    }
}

// ---------------- Flash attention: BQ=64, BK=64, causal, GQA (rep=8) ----------------
// smem: QsT[128][68] | KV (K transposed [128][68] then V [64][132]) | Ps[64][68]
#define Q_PITCH 68
#define V_PITCH 132
#define SM_QST   (128 * Q_PITCH)
#define SM_KV    (128 * Q_PITCH)          // >= 64*132
#define SM_PS    (64 * Q_PITCH)
#define FLASH_SMEM_FLOATS (SM_QST + SM_KV + SM_PS)
#define FLASH_SMEM_BYTES  (FLASH_SMEM_FLOATS * 4)

__global__ __launch_bounds__(256, 2) void flash_attn_kernel()
{
    extern __shared__ float sm[];
    float* QsT = sm;                    // [d][tok], pitch 68
    float* KV  = sm + SM_QST;           // K: [d][tok] pitch 68;  V: [tok][d] pitch 132
    float* Ps  = sm + SM_QST + SM_KV;   // [row][col], pitch 68

    const int tid = threadIdx.x;
    const int tx = tid & 15, ty = tid >> 4;
    const int ltok = tid >> 2, dg = tid & 3;

    const int qb = blockIdx.x;          // query block (64 rows)
    const int bh = blockIdx.y;
    const int b = bh >> 4, h = bh & 15, kvh = h >> 3;

    const float* qbase = g_qkv + (size_t)(b * S_LEN + qb * 64) * QKV_N + h * HD;
    const float* kbase = g_qkv + (size_t)(b * S_LEN) * QKV_N + (NH + kvh) * HD;
    const float* vbase = g_qkv + (size_t)(b * S_LEN) * QKV_N + (NH + NKV + kvh) * HD;

    // load Q transposed into QsT
#pragma unroll
    for (int i = 0; i < 8; i++) {
        int d = (dg + i * 4) * 4;
        float4 v = *(const float4*)(qbase + (size_t)ltok * QKV_N + d);
        QsT[(d + 0) * Q_PITCH + ltok] = v.x;
        QsT[(d + 1) * Q_PITCH + ltok] = v.y;
        QsT[(d + 2) * Q_PITCH + ltok] = v.z;
        QsT[(d + 3) * Q_PITCH + ltok] = v.w;
    }

    float m[4], l[4], O[4][8];
#pragma unroll
    for (int i = 0; i < 4; i++) {
        m[i] = -1e30f; l[i] = 0.0f;
#pragma unroll
        for (int j = 0; j < 8; j++) O[i][j] = 0.0f;
    }
    __syncthreads();

    for (int kt = 0; kt <= qb; kt++) {
        // ---- load K tile transposed into KV ----
#pragma unroll
        for (int i = 0; i < 8; i++) {
            int d = (dg + i * 4) * 4;
            float4 v = *(const float4*)(kbase + (size_t)(kt * 64 + ltok) * QKV_N + d);
            KV[(d + 0) * Q_PITCH + ltok] = v.x;
            KV[(d + 1) * Q_PITCH + ltok] = v.y;
            KV[(d + 2) * Q_PITCH + ltok] = v.z;
            KV[(d + 3) * Q_PITCH + ltok] = v.w;
        }
        __syncthreads();

        // ---- scores: s[i][j] = Q[ty*4+i] . K[tx*4+j] ----
        float s[4][4];
#pragma unroll
        for (int i = 0; i < 4; i++)
#pragma unroll
            for (int j = 0; j < 4; j++) s[i][j] = 0.0f;

        for (int d = 0; d < 128; d++) {
            float4 q = *(const float4*)&QsT[d * Q_PITCH + ty * 4];
            float4 k = *(const float4*)&KV[d * Q_PITCH + tx * 4];
            float qr[4] = {q.x, q.y, q.z, q.w};
            float kr[4] = {k.x, k.y, k.z, k.w};
#pragma unroll
            for (int i = 0; i < 4; i++)
#pragma unroll
                for (int j = 0; j < 4; j++)
                    s[i][j] = fmaf(qr[i], kr[j], s[i][j]);
        }

        // scale + causal mask (only diagonal tile needs masking)
#pragma unroll
        for (int i = 0; i < 4; i++) {
            int rg = qb * 64 + ty * 4 + i;
#pragma unroll
            for (int j = 0; j < 4; j++) {
                int cg = kt * 64 + tx * 4 + j;
                s[i][j] *= SCALE;
                if (kt == qb && cg > rg) s[i][j] = -1e30f;
            }
        }

        // ---- online softmax (row stats via half-warp shfl; rows owned per-thread) ----
#pragma unroll
        for (int i = 0; i < 4; i++) {
            float tm = fmaxf(fmaxf(s[i][0], s[i][1]), fmaxf(s[i][2], s[i][3]));
#pragma unroll
            for (int o = 8; o >= 1; o >>= 1)
                tm = fmaxf(tm, __shfl_xor_sync(0xffffffffu, tm, o));
            float mn = fmaxf(m[i], tm);
            float alpha = __expf(m[i] - mn);
            float psum = 0.0f;
            int prow = (ty * 4 + i) * Q_PITCH + tx * 4;
#pragma unroll
            for (int j = 0; j < 4; j++) {
                float p = __expf(s[i][j] - mn);
                Ps[prow + j] = p;
                psum += p;
            }
#pragma unroll
            for (int o = 8; o >= 1; o >>= 1)
                psum += __shfl_xor_sync(0xffffffffu, psum, o);
            l[i] = l[i] * alpha + psum;
            m[i] = mn;
#pragma unroll
            for (int j = 0; j < 8; j++) O[i][j] *= alpha;
        }
        __syncthreads();   // P written, K reads done -> safe to overwrite KV with V

        // ---- load V tile row-major into KV ----
#pragma unroll
        for (int i = 0; i < 8; i++) {
            int d = (dg + i * 4) * 4;
            float4 v = *(const float4*)(vbase + (size_t)(kt * 64 + ltok) * QKV_N + d);
            *(float4*)&KV[ltok * V_PITCH + d] = v;
        }
        __syncthreads();

        // ---- O += P @ V  (thread cols: tx*4..+3 and 64+tx*4..+3) ----
        for (int c = 0; c < 64; c++) {
            float pr[4];
#pragma unroll
            for (int i = 0; i < 4; i++) pr[i] = Ps[(ty * 4 + i) * Q_PITCH + c];
            float4 v0 = *(const float4*)&KV[c * V_PITCH + tx * 4];
            float4 v1 = *(const float4*)&KV[c * V_PITCH + 64 + tx * 4];
            float vr[8] = {v0.x, v0.y, v0.z, v0.w, v1.x, v1.y, v1.z, v1.w};
#pragma unroll
            for (int i = 0; i < 4; i++)
#pragma unroll
                for (int j = 0; j < 8; j++)
                    O[i][j] = fmaf(pr[i], vr[j], O[i][j]);
        }
        __syncthreads();   // PV done reading KV/Ps before next iteration overwrites
    }

    // ---- epilogue: O /= l, write to g_attn ----
#pragma unroll
    for (int i = 0; i < 4; i++) {
        float inv = 1.0f / l[i];
        int row = b * S_LEN + qb * 64 + ty * 4 + i;
        float4 c0, c1;
        c0.x = O[i][0] * inv; c0.y = O[i][1] * inv; c0.z = O[i][2] * inv; c0.w = O[i][3] * inv;
        c1.x = O[i][4] * inv; c1.y = O[i][5] * inv; c1.z = O[i][6] * inv; c1.w = O[i][7] * inv;
        *(float4*)&g_attn[(size_t)row * OUT_N + h * HD + tx * 4]      = c0;
        *(float4*)&g_attn[(size_t)row * OUT_N + h * HD + 64 + tx * 4] = c1;
    }
}

// ---------------- launch ----------------
extern "C" void kernel_launch(void* const* d_in, const int* in_sizes, int n_in,
                              void* d_out, int out_size)
{
    // identify inputs by element count (all distinct)
    const int*   positions = nullptr;
    const float* hidden = nullptr;
    const float* Wqkv = nullptr;
    const float* bqkv = nullptr;
    const float* Wo = nullptr;
    for (int i = 0; i < n_in; i++) {
        switch (in_sizes[i]) {
            case NTOK:                 positions = (const int*)d_in[i]; break;   // 4096
            case NTOK * HID_D:         hidden = (const float*)d_in[i]; break;    // 8388608
            case HID_D * QKV_N:        Wqkv = (const float*)d_in[i]; break;      // 5242880
            case QKV_N:                bqkv = (const float*)d_in[i]; break;      // 2560
            case OUT_N * HID_D:        Wo = (const float*)d_in[i]; break;        // 4194304
        }
    }

    float* qkv;  cudaGetSymbolAddress((void**)&qkv,  g_qkv);
    float* attn; cudaGetSymbolAddress((void**)&attn, g_attn);
    float* out = (float*)d_out;

    // 1. RoPE table
    rope_table_kernel<<<(S_LEN * 64 + 255) / 256, 256>>>();

    // 2. QKV projection (+bias)
    {
        dim3 grid(QKV_N / 128, NTOK / 128);
        sgemm_kernel<true><<<grid, 256>>>(hidden, Wqkv, bqkv, qkv, NTOK, QKV_N, HID_D);
    }

    // 3. RoPE apply
    {
        size_t total = (size_t)NTOK * (NH + NKV) * 64;
        rope_apply_kernel<<<(unsigned)((total + 255) / 256), 256>>>(positions);
    }

    // 4. Flash attention
    {
        cudaFuncSetAttribute(flash_attn_kernel,
                             cudaFuncAttributeMaxDynamicSharedMemorySize, FLASH_SMEM_BYTES);
        dim3 grid(S_LEN / 64, BATCH * NH);
        flash_attn_kernel<<<grid, 256, FLASH_SMEM_BYTES>>>();
    }

    // 5. Output projection
    {
        dim3 grid(HID_D / 128, NTOK / 128);
        sgemm_kernel<false><<<grid, 256>>>(attn, Wo, nullptr, out, NTOK, HID_D, OUT_N);
    }
}

// round 6
// speedup vs baseline: 1.2878x; 1.2878x over previous
#include <cuda_runtime.h>
#include <math.h>

#define BATCH  2
#define S_LEN  2048
#define HID_D  2048
#define NH     16
#define NKV    2
#define HD     128
#define QKV_N  ((NH + 2*NKV) * HD)   // 2560
#define NTOK   (BATCH * S_LEN)       // 4096
#define OUT_N  (NH * HD)             // 2048
#define SCALE  0.08838834764831843f  // 128^-0.5

// ---------------- scratch (device globals; no allocation allowed) ----------------
__device__ __align__(16) float g_qkv[(size_t)NTOK * QKV_N];    // 41.9 MB
__device__ __align__(16) float g_attn[(size_t)NTOK * OUT_N];   // 33.5 MB
__device__ __align__(16) float g_cs[(size_t)S_LEN * HD];       // [s][0..63]=cos, [64..127]=sin

// ---------------- RoPE cos/sin table (fp64 for angle accuracy) ----------------
__global__ void rope_table_kernel() {
    int idx = blockIdx.x * blockDim.x + threadIdx.x;
    if (idx >= S_LEN * 64) return;
    int s = idx >> 6, i = idx & 63;
    double inv = pow(1000000.0, -(double)i / 64.0);
    double ang = (double)s * inv;
    g_cs[s * HD + i]      = (float)cos(ang);
    g_cs[s * HD + 64 + i] = (float)sin(ang);
}

// ---------------- RoPE apply (q: 16 heads, k: 2 heads) ----------------
__global__ void rope_apply_kernel(const int* __restrict__ positions) {
    size_t idx = (size_t)blockIdx.x * blockDim.x + threadIdx.x;
    const size_t total = (size_t)NTOK * (NH + NKV) * 64;
    if (idx >= total) return;
    int i    = idx & 63;
    size_t r = idx >> 6;
    int head = (int)(r % (NH + NKV));
    int t    = (int)(r / (NH + NKV));
    int pos  = positions[t];
    float c  = g_cs[pos * HD + i];
    float sn = g_cs[pos * HD + 64 + i];
    int off  = (head < NH) ? head * HD : (NH * HD + (head - NH) * HD);
    float* p = g_qkv + (size_t)t * QKV_N + off;
    float x1 = p[i], x2 = p[i + 64];
    p[i]      = x1 * c - x2 * sn;
    p[i + 64] = x2 * c + x1 * sn;
}

// ---------------- TF32 tensor-core GEMM: C[M,N] = A[M,K] @ B[K,N] (+bias) ----------------
// 128x128x16 CTA tile, 8 warps (2x4), warp tile 64x32, mma.m16n8k8 tf32.
// Smem pitch 136 words -> fragment LDS banks (8k+idx)%32 = perfect permutation.

__device__ __forceinline__ unsigned f2tf32(float x) {
    unsigned r;
    asm("cvt.rna.tf32.f32 %0, %1;" : "=r"(r) : "f"(x));
    return r;
}

#define MMA_TF32(d, a, b)                                                     \
    asm volatile("mma.sync.aligned.m16n8k8.row.col.f32.tf32.tf32.f32 "        \
                 "{%0,%1,%2,%3}, {%4,%5,%6,%7}, {%8,%9}, {%0,%1,%2,%3};"      \
                 : "+f"(d[0]), "+f"(d[1]), "+f"(d[2]), "+f"(d[3])             \
                 : "r"(a[0]), "r"(a[1]), "r"(a[2]), "r"(a[3]),                \
                   "r"(b[0]), "r"(b[1]))

template <bool BIAS>
__global__ __launch_bounds__(256) void gemm_tf32_kernel(
    const float* __restrict__ A, const float* __restrict__ B,
    const float* __restrict__ bias, float* __restrict__ C,
    int M, int N, int K)
{
    __shared__ unsigned As[2][16][136];   // [k][m]
    __shared__ unsigned Bs[2][16][136];   // [k][n]

    const int tid = threadIdx.x;
    const int bm = blockIdx.y * 128, bn = blockIdx.x * 128;

    // global load mapping
    const int arow = tid & 127, ak = (tid >> 7) * 8;    // A tile: 128 rows x 16 cols
    const int brow = tid >> 4,  bcol = (tid & 15) * 8;  // B tile: 16 rows x 128 cols
    const float* Aptr = A + (size_t)(bm + arow) * K + ak;
    const float* Bptr = B + (size_t)brow * N + bn + bcol;

    const int w  = tid >> 5;
    const int wm = (w >> 2) * 64, wn = (w & 3) * 32;
    const int lane = tid & 31, grp = lane >> 2, tig = lane & 3;

    float acc[4][4][4];
#pragma unroll
    for (int mt = 0; mt < 4; mt++)
#pragma unroll
        for (int nt = 0; nt < 4; nt++)
#pragma unroll
            for (int r = 0; r < 4; r++) acc[mt][nt][r] = 0.0f;

    const int nk = K >> 4;

    float4 av0 = *(const float4*)(Aptr);
    float4 av1 = *(const float4*)(Aptr + 4);
    float4 bv0 = *(const float4*)(Bptr);
    float4 bv1 = *(const float4*)(Bptr + 4);

    // store stage 0
    {
        As[0][ak + 0][arow] = f2tf32(av0.x); As[0][ak + 1][arow] = f2tf32(av0.y);
        As[0][ak + 2][arow] = f2tf32(av0.z); As[0][ak + 3][arow] = f2tf32(av0.w);
        As[0][ak + 4][arow] = f2tf32(av1.x); As[0][ak + 5][arow] = f2tf32(av1.y);
        As[0][ak + 6][arow] = f2tf32(av1.z); As[0][ak + 7][arow] = f2tf32(av1.w);
        uint4 u0 = make_uint4(f2tf32(bv0.x), f2tf32(bv0.y), f2tf32(bv0.z), f2tf32(bv0.w));
        uint4 u1 = make_uint4(f2tf32(bv1.x), f2tf32(bv1.y), f2tf32(bv1.z), f2tf32(bv1.w));
        *(uint4*)&Bs[0][brow][bcol]     = u0;
        *(uint4*)&Bs[0][brow][bcol + 4] = u1;
    }
    __syncthreads();

    int buf = 0;
    for (int kt = 0; kt < nk; kt++) {
        if (kt + 1 < nk) {
            av0 = *(const float4*)(Aptr + (kt + 1) * 16);
            av1 = *(const float4*)(Aptr + (kt + 1) * 16 + 4);
            bv0 = *(const float4*)(Bptr + (size_t)(kt + 1) * 16 * N);
            bv1 = *(const float4*)(Bptr + (size_t)(kt + 1) * 16 * N + 4);
        }
#pragma unroll
        for (int kk = 0; kk < 16; kk += 8) {
            unsigned af[4][4], bf[4][2];
#pragma unroll
            for (int mt = 0; mt < 4; mt++) {
                int r = wm + mt * 16 + grp;
                af[mt][0] = As[buf][kk + tig][r];
                af[mt][1] = As[buf][kk + tig][r + 8];
                af[mt][2] = As[buf][kk + tig + 4][r];
                af[mt][3] = As[buf][kk + tig + 4][r + 8];
            }
#pragma unroll
            for (int nt = 0; nt < 4; nt++) {
                int c = wn + nt * 8 + grp;
                bf[nt][0] = Bs[buf][kk + tig][c];
                bf[nt][1] = Bs[buf][kk + tig + 4][c];
            }
#pragma unroll
            for (int mt = 0; mt < 4; mt++)
#pragma unroll
                for (int nt = 0; nt < 4; nt++)
                    MMA_TF32(acc[mt][nt], af[mt], bf[nt]);
        }
        if (kt + 1 < nk) {
            __syncthreads();
            int nb = buf ^ 1;
            As[nb][ak + 0][arow] = f2tf32(av0.x); As[nb][ak + 1][arow] = f2tf32(av0.y);
            As[nb][ak + 2][arow] = f2tf32(av0.z); As[nb][ak + 3][arow] = f2tf32(av0.w);
            As[nb][ak + 4][arow] = f2tf32(av1.x); As[nb][ak + 5][arow] = f2tf32(av1.y);
            As[nb][ak + 6][arow] = f2tf32(av1.z); As[nb][ak + 7][arow] = f2tf32(av1.w);
            uint4 u0 = make_uint4(f2tf32(bv0.x), f2tf32(bv0.y), f2tf32(bv0.z), f2tf32(bv0.w));
            uint4 u1 = make_uint4(f2tf32(bv1.x), f2tf32(bv1.y), f2tf32(bv1.z), f2tf32(bv1.w));
            *(uint4*)&Bs[nb][brow][bcol]     = u0;
            *(uint4*)&Bs[nb][brow][bcol + 4] = u1;
            buf = nb;
            __syncthreads();
        }
    }

    // epilogue: acc[mt][nt] -> rows (bm+wm+mt*16+grp, +8), cols (bn+wn+nt*8+2*tig, +1)
#pragma unroll
    for (int nt = 0; nt < 4; nt++) {
        int c = bn + wn + nt * 8 + tig * 2;
        float b0 = 0.0f, b1 = 0.0f;
        if (BIAS) { b0 = bias[c]; b1 = bias[c + 1]; }
#pragma unroll
        for (int mt = 0; mt < 4; mt++) {
            int r = bm + wm + mt * 16 + grp;
            float2 v0, v1;
            v0.x = acc[mt][nt][0] + b0; v0.y = acc[mt][nt][1] + b1;
            v1.x = acc[mt][nt][2] + b0; v1.y = acc[mt][nt][3] + b1;
            *(float2*)&C[(size_t)r * N + c]       = v0;
            *(float2*)&C[(size_t)(r + 8) * N + c] = v1;
        }
    }
}

// ---------------- Flash attention: BQ=64, BK=64, causal, GQA (rep=8) ----------------
// smem: QsT[128][68] | KV (K transposed [128][68] then V [64][132]) | Ps[64][68]
#define Q_PITCH 68
#define V_PITCH 132
#define SM_QST   (128 * Q_PITCH)
#define SM_KV    (128 * Q_PITCH)          // >= 64*132
#define SM_PS    (64 * Q_PITCH)
#define FLASH_SMEM_FLOATS (SM_QST + SM_KV + SM_PS)
#define FLASH_SMEM_BYTES  (FLASH_SMEM_FLOATS * 4)

__global__ __launch_bounds__(256, 2) void flash_attn_kernel()
{
    extern __shared__ float sm[];
    float* QsT = sm;                    // [d][tok], pitch 68
    float* KV  = sm + SM_QST;           // K: [d][tok] pitch 68;  V: [tok][d] pitch 132
    float* Ps  = sm + SM_QST + SM_KV;   // [row][col], pitch 68

    const int tid = threadIdx.x;
    const int tx = tid & 15, ty = tid >> 4;
    const int ltok = tid >> 2, dg = tid & 3;

    const int qb = blockIdx.x;          // query block (64 rows)
    const int bh = blockIdx.y;
    const int b = bh >> 4, h = bh & 15, kvh = h >> 3;

    const float* qbase = g_qkv + (size_t)(b * S_LEN + qb * 64) * QKV_N + h * HD;
    const float* kbase = g_qkv + (size_t)(b * S_LEN) * QKV_N + (NH + kvh) * HD;
    const float* vbase = g_qkv + (size_t)(b * S_LEN) * QKV_N + (NH + NKV + kvh) * HD;

    // load Q transposed into QsT
#pragma unroll
    for (int i = 0; i < 8; i++) {
        int d = (dg + i * 4) * 4;
        float4 v = *(const float4*)(qbase + (size_t)ltok * QKV_N + d);
        QsT[(d + 0) * Q_PITCH + ltok] = v.x;
        QsT[(d + 1) * Q_PITCH + ltok] = v.y;
        QsT[(d + 2) * Q_PITCH + ltok] = v.z;
        QsT[(d + 3) * Q_PITCH + ltok] = v.w;
    }

    float m[4], l[4], O[4][8];
#pragma unroll
    for (int i = 0; i < 4; i++) {
        m[i] = -1e30f; l[i] = 0.0f;
#pragma unroll
        for (int j = 0; j < 8; j++) O[i][j] = 0.0f;
    }
    __syncthreads();

    for (int kt = 0; kt <= qb; kt++) {
        // ---- load K tile transposed into KV ----
#pragma unroll
        for (int i = 0; i < 8; i++) {
            int d = (dg + i * 4) * 4;
            float4 v = *(const float4*)(kbase + (size_t)(kt * 64 + ltok) * QKV_N + d);
            KV[(d + 0) * Q_PITCH + ltok] = v.x;
            KV[(d + 1) * Q_PITCH + ltok] = v.y;
            KV[(d + 2) * Q_PITCH + ltok] = v.z;
            KV[(d + 3) * Q_PITCH + ltok] = v.w;
        }
        __syncthreads();

        // ---- scores: s[i][j] = Q[ty*4+i] . K[tx*4+j] ----
        float s[4][4];
#pragma unroll
        for (int i = 0; i < 4; i++)
#pragma unroll
            for (int j = 0; j < 4; j++) s[i][j] = 0.0f;

        for (int d = 0; d < 128; d++) {
            float4 q = *(const float4*)&QsT[d * Q_PITCH + ty * 4];
            float4 k = *(const float4*)&KV[d * Q_PITCH + tx * 4];
            float qr[4] = {q.x, q.y, q.z, q.w};
            float kr[4] = {k.x, k.y, k.z, k.w};
#pragma unroll
            for (int i = 0; i < 4; i++)
#pragma unroll
                for (int j = 0; j < 4; j++)
                    s[i][j] = fmaf(qr[i], kr[j], s[i][j]);
        }

        // scale + causal mask (only diagonal tile needs masking)
#pragma unroll
        for (int i = 0; i < 4; i++) {
            int rg = qb * 64 + ty * 4 + i;
#pragma unroll
            for (int j = 0; j < 4; j++) {
                int cg = kt * 64 + tx * 4 + j;
                s[i][j] *= SCALE;
                if (kt == qb && cg > rg) s[i][j] = -1e30f;
            }
        }

        // ---- online softmax (row stats via half-warp shfl; rows owned per-thread) ----
#pragma unroll
        for (int i = 0; i < 4; i++) {
            float tm = fmaxf(fmaxf(s[i][0], s[i][1]), fmaxf(s[i][2], s[i][3]));
#pragma unroll
            for (int o = 8; o >= 1; o >>= 1)
                tm = fmaxf(tm, __shfl_xor_sync(0xffffffffu, tm, o));
            float mn = fmaxf(m[i], tm);
            float alpha = __expf(m[i] - mn);
            float psum = 0.0f;
            int prow = (ty * 4 + i) * Q_PITCH + tx * 4;
#pragma unroll
            for (int j = 0; j < 4; j++) {
                float p = __expf(s[i][j] - mn);
                Ps[prow + j] = p;
                psum += p;
            }
#pragma unroll
            for (int o = 8; o >= 1; o >>= 1)
                psum += __shfl_xor_sync(0xffffffffu, psum, o);
            l[i] = l[i] * alpha + psum;
            m[i] = mn;
#pragma unroll
            for (int j = 0; j < 8; j++) O[i][j] *= alpha;
        }
        __syncthreads();   // P written, K reads done -> safe to overwrite KV with V

        // ---- load V tile row-major into KV ----
#pragma unroll
        for (int i = 0; i < 8; i++) {
            int d = (dg + i * 4) * 4;
            float4 v = *(const float4*)(vbase + (size_t)(kt * 64 + ltok) * QKV_N + d);
            *(float4*)&KV[ltok * V_PITCH + d] = v;
        }
        __syncthreads();

        // ---- O += P @ V  (thread cols: tx*4..+3 and 64+tx*4..+3) ----
        for (int c = 0; c < 64; c++) {
            float pr[4];
#pragma unroll
            for (int i = 0; i < 4; i++) pr[i] = Ps[(ty * 4 + i) * Q_PITCH + c];
            float4 v0 = *(const float4*)&KV[c * V_PITCH + tx * 4];
            float4 v1 = *(const float4*)&KV[c * V_PITCH + 64 + tx * 4];
            float vr[8] = {v0.x, v0.y, v0.z, v0.w, v1.x, v1.y, v1.z, v1.w};
#pragma unroll
            for (int i = 0; i < 4; i++)
#pragma unroll
                for (int j = 0; j < 8; j++)
                    O[i][j] = fmaf(pr[i], vr[j], O[i][j]);
        }
        __syncthreads();   // PV done reading KV/Ps before next iteration overwrites
    }

    // ---- epilogue: O /= l, write to g_attn ----
#pragma unroll
    for (int i = 0; i < 4; i++) {
        float inv = 1.0f / l[i];
        int row = b * S_LEN + qb * 64 + ty * 4 + i;
        float4 c0, c1;
        c0.x = O[i][0] * inv; c0.y = O[i][1] * inv; c0.z = O[i][2] * inv; c0.w = O[i][3] * inv;
        c1.x = O[i][4] * inv; c1.y = O[i][5] * inv; c1.z = O[i][6] * inv; c1.w = O[i][7] * inv;
        *(float4*)&g_attn[(size_t)row * OUT_N + h * HD + tx * 4]      = c0;
        *(float4*)&g_attn[(size_t)row * OUT_N + h * HD + 64 + tx * 4] = c1;
    }
}

// ---------------- launch ----------------
extern "C" void kernel_launch(void* const* d_in, const int* in_sizes, int n_in,
                              void* d_out, int out_size)
{
    // identify inputs by element count (all distinct)
    const int*   positions = nullptr;
    const float* hidden = nullptr;
    const float* Wqkv = nullptr;
    const float* bqkv = nullptr;
    const float* Wo = nullptr;
    for (int i = 0; i < n_in; i++) {
        switch (in_sizes[i]) {
            case NTOK:                 positions = (const int*)d_in[i]; break;   // 4096
            case NTOK * HID_D:         hidden = (const float*)d_in[i]; break;    // 8388608
            case HID_D * QKV_N:        Wqkv = (const float*)d_in[i]; break;      // 5242880
            case QKV_N:                bqkv = (const float*)d_in[i]; break;      // 2560
            case OUT_N * HID_D:        Wo = (const float*)d_in[i]; break;        // 4194304
        }
    }

    float* qkv;  cudaGetSymbolAddress((void**)&qkv,  g_qkv);
    float* attn; cudaGetSymbolAddress((void**)&attn, g_attn);
    float* out = (float*)d_out;

    // 1. RoPE table
    rope_table_kernel<<<(S_LEN * 64 + 255) / 256, 256>>>();

    // 2. QKV projection (+bias), tf32 tensor cores
    {
        dim3 grid(QKV_N / 128, NTOK / 128);
        gemm_tf32_kernel<true><<<grid, 256>>>(hidden, Wqkv, bqkv, qkv, NTOK, QKV_N, HID_D);
    }

    // 3. RoPE apply
    {
        size_t total = (size_t)NTOK * (NH + NKV) * 64;
        rope_apply_kernel<<<(unsigned)((total + 255) / 256), 256>>>(positions);
    }

    // 4. Flash attention
    {
        cudaFuncSetAttribute(flash_attn_kernel,
                             cudaFuncAttributeMaxDynamicSharedMemorySize, FLASH_SMEM_BYTES);
        dim3 grid(S_LEN / 64, BATCH * NH);
        flash_attn_kernel<<<grid, 256, FLASH_SMEM_BYTES>>>();
    }

    // 5. Output projection, tf32 tensor cores
    {
        dim3 grid(HID_D / 128, NTOK / 128);
        gemm_tf32_kernel<false><<<grid, 256>>>(attn, Wo, nullptr, out, NTOK, HID_D, OUT_N);
    }
}

// round 9
// speedup vs baseline: 1.2887x; 1.0007x over previous
#include <cuda_runtime.h>
#include <cuda_fp16.h>
#include <cstdint>
#include <math.h>

#define BATCH  2
#define S_LEN  2048
#define HID_D  2048
#define NH     16
#define NKV    2
#define HD     128
#define QKV_N  ((NH + 2*NKV) * HD)   // 2560
#define NTOK   (BATCH * S_LEN)       // 4096
#define OUT_N  (NH * HD)             // 2048
#define SCALE  0.08838834764831843f  // 128^-0.5

// ---------------- scratch (device globals; no allocation allowed) ----------------
__device__ __align__(16) float g_qkv[(size_t)NTOK * QKV_N];      // 41.9 MB
__device__ __align__(16) float g_attn[(size_t)NTOK * OUT_N];     // 33.5 MB
__device__ __align__(16) float g_cs[(size_t)S_LEN * HD];
__device__ __align__(16) float g_wqkvT[(size_t)QKV_N * HID_D];   // Wqkv^T: [N][K]
__device__ __align__(16) float g_woT[(size_t)HID_D * OUT_N];     // Wo^T:   [N][K]

// ---------------- RoPE cos/sin table (fp64 for angle accuracy) ----------------
__global__ void rope_table_kernel() {
    int idx = blockIdx.x * blockDim.x + threadIdx.x;
    if (idx >= S_LEN * 64) return;
    int s = idx >> 6, i = idx & 63;
    double inv = pow(1000000.0, -(double)i / 64.0);
    double ang = (double)s * inv;
    g_cs[s * HD + i]      = (float)cos(ang);
    g_cs[s * HD + 64 + i] = (float)sin(ang);
}

// ---------------- RoPE apply (q: 16 heads, k: 2 heads) ----------------
__global__ void rope_apply_kernel(const int* __restrict__ positions) {
    size_t idx = (size_t)blockIdx.x * blockDim.x + threadIdx.x;
    const size_t total = (size_t)NTOK * (NH + NKV) * 64;
    if (idx >= total) return;
    int i    = idx & 63;
    size_t r = idx >> 6;
    int head = (int)(r % (NH + NKV));
    int t    = (int)(r / (NH + NKV));
    int pos  = positions[t];
    float c  = g_cs[pos * HD + i];
    float sn = g_cs[pos * HD + 64 + i];
    int off  = (head < NH) ? head * HD : (NH * HD + (head - NH) * HD);
    float* p = g_qkv + (size_t)t * QKV_N + off;
    float x1 = p[i], x2 = p[i + 64];
    p[i]      = x1 * c - x2 * sn;
    p[i + 64] = x2 * c + x1 * sn;
}

// ---------------- weight transpose: out[N][K] = in[K][N] ----------------
__global__ void transpose_kernel(const float* __restrict__ in, float* __restrict__ out,
                                 int rows, int cols) {
    __shared__ float t[32][33];
    int x = blockIdx.x * 32 + threadIdx.x;
    int y = blockIdx.y * 32 + threadIdx.y;
#pragma unroll
    for (int j = 0; j < 32; j += 8)
        t[threadIdx.y + j][threadIdx.x] = in[(size_t)(y + j) * cols + x];
    __syncthreads();
    x = blockIdx.y * 32 + threadIdx.x;
    y = blockIdx.x * 32 + threadIdx.y;
#pragma unroll
    for (int j = 0; j < 32; j += 8)
        out[(size_t)(y + j) * rows + x] = t[threadIdx.x][threadIdx.y + j];
}

// ============ fp16 tensor-core GEMM: C[M,N] = A[M,K] @ Bt[N,K]^T (+bias) ============
// 128x128 CTA tile, 8 warps (2x4), warp tile 64x32, mma.m16n8k16 fp16, fp32 accum.
// K-chunk 32 (two k16 steps), double-buffered half2 smem [k2][row], pitch 136:
//   fragment reads  -> bank = tig*8 + grp  (perfect permutation, conflict-free)
//   fill stores     -> one thread per row  (32 consecutive rows/warp, conflict-free)

__device__ __forceinline__ unsigned packh2(float x, float y) {
    __half2 h = __floats2half2_rn(x, y);
    return *(unsigned*)&h;
}

#define MMA_F16(d, a, b)                                                      \
    asm volatile("mma.sync.aligned.m16n8k16.row.col.f32.f16.f16.f32 "         \
                 "{%0,%1,%2,%3}, {%4,%5,%6,%7}, {%8,%9}, {%0,%1,%2,%3};"      \
                 : "+f"(d[0]), "+f"(d[1]), "+f"(d[2]), "+f"(d[3])             \
                 : "r"(a[0]), "r"(a[1]), "r"(a[2]), "r"(a[3]),                \
                   "r"(b[0]), "r"(b[1]))

template <bool BIAS>
__global__ __launch_bounds__(256) void gemm_f16_kernel(
    const float* __restrict__ A, const float* __restrict__ Bt,
    const float* __restrict__ bias, float* __restrict__ C,
    int M, int N, int K)
{
    __shared__ unsigned As2[2][16][136];   // half2 packed: [k/2][m]
    __shared__ unsigned Bs2[2][16][136];   // half2 packed: [k/2][n]

    const int tid = threadIdx.x;
    const int bm = blockIdx.y * 128, bn = blockIdx.x * 128;

    // fill mapping: one thread per row, half-K split across tid bit 7
    const int frow = tid & 127;
    const int fkh  = (tid >> 7) * 16;         // 0 or 16 (float offset in chunk)
    const int fk2  = fkh >> 1;                // 0 or 8  (half2 row base)
    const float* Aptr = A  + (size_t)(bm + frow) * K + fkh;
    const float* Bptr = Bt + (size_t)(bn + frow) * K + fkh;

    const int w  = tid >> 5;
    const int wm = (w >> 2) * 64, wn = (w & 3) * 32;
    const int lane = tid & 31, grp = lane >> 2, tig = lane & 3;

    float acc[4][4][4];
#pragma unroll
    for (int mt = 0; mt < 4; mt++)
#pragma unroll
        for (int nt = 0; nt < 4; nt++)
#pragma unroll
            for (int r = 0; r < 4; r++) acc[mt][nt][r] = 0.0f;

    const int nk = K >> 5;   // chunks of 32
    float4 ar[4], br[4];

#pragma unroll
    for (int j = 0; j < 4; j++) {
        ar[j] = *(const float4*)(Aptr + j * 4);
        br[j] = *(const float4*)(Bptr + j * 4);
    }
#pragma unroll
    for (int j = 0; j < 4; j++) {
        As2[0][fk2 + j * 2 + 0][frow] = packh2(ar[j].x, ar[j].y);
        As2[0][fk2 + j * 2 + 1][frow] = packh2(ar[j].z, ar[j].w);
        Bs2[0][fk2 + j * 2 + 0][frow] = packh2(br[j].x, br[j].y);
        Bs2[0][fk2 + j * 2 + 1][frow] = packh2(br[j].z, br[j].w);
    }
    __syncthreads();

    int buf = 0;
    for (int kt = 0; kt < nk; kt++) {
        if (kt + 1 < nk) {
#pragma unroll
            for (int j = 0; j < 4; j++) {
                ar[j] = *(const float4*)(Aptr + (kt + 1) * 32 + j * 4);
                br[j] = *(const float4*)(Bptr + (kt + 1) * 32 + j * 4);
            }
        }
#pragma unroll
        for (int ks = 0; ks < 2; ks++) {
            const int kb = ks * 8;
            unsigned af[4][4], bf[4][2];
#pragma unroll
            for (int mt = 0; mt < 4; mt++) {
                int r = wm + mt * 16 + grp;
                af[mt][0] = As2[buf][kb + tig][r];
                af[mt][1] = As2[buf][kb + tig][r + 8];
                af[mt][2] = As2[buf][kb + tig + 4][r];
                af[mt][3] = As2[buf][kb + tig + 4][r + 8];
            }
#pragma unroll
            for (int nt = 0; nt < 4; nt++) {
                int c = wn + nt * 8 + grp;
                bf[nt][0] = Bs2[buf][kb + tig][c];
                bf[nt][1] = Bs2[buf][kb + tig + 4][c];
            }
#pragma unroll
            for (int mt = 0; mt < 4; mt++)
#pragma unroll
                for (int nt = 0; nt < 4; nt++)
                    MMA_F16(acc[mt][nt], af[mt], bf[nt]);
        }
        if (kt + 1 < nk) {
            __syncthreads();
            int nb = buf ^ 1;
#pragma unroll
            for (int j = 0; j < 4; j++) {
                As2[nb][fk2 + j * 2 + 0][frow] = packh2(ar[j].x, ar[j].y);
                As2[nb][fk2 + j * 2 + 1][frow] = packh2(ar[j].z, ar[j].w);
                Bs2[nb][fk2 + j * 2 + 0][frow] = packh2(br[j].x, br[j].y);
                Bs2[nb][fk2 + j * 2 + 1][frow] = packh2(br[j].z, br[j].w);
            }
            buf = nb;
            __syncthreads();
        }
    }

    // epilogue: acc[mt][nt] -> rows (bm+wm+mt*16+grp, +8), cols (bn+wn+nt*8+2*tig, +1)
#pragma unroll
    for (int nt = 0; nt < 4; nt++) {
        int c = bn + wn + nt * 8 + tig * 2;
        float b0 = 0.0f, b1 = 0.0f;
        if (BIAS) { b0 = bias[c]; b1 = bias[c + 1]; }
#pragma unroll
        for (int mt = 0; mt < 4; mt++) {
            int r = bm + wm + mt * 16 + grp;
            float2 v0, v1;
            v0.x = acc[mt][nt][0] + b0; v0.y = acc[mt][nt][1] + b1;
            v1.x = acc[mt][nt][2] + b0; v1.y = acc[mt][nt][3] + b1;
            *(float2*)&C[(size_t)r * N + c]       = v0;
            *(float2*)&C[(size_t)(r + 8) * N + c] = v1;
        }
    }
}

// ---------------- Flash attention: BQ=64, BK=64, causal, GQA (rep=8) ----------------
#define Q_PITCH 68
#define V_PITCH 132
#define SM_QST   (128 * Q_PITCH)
#define SM_KV    (128 * Q_PITCH)
#define SM_PS    (64 * Q_PITCH)
#define FLASH_SMEM_FLOATS (SM_QST + SM_KV + SM_PS)
#define FLASH_SMEM_BYTES  (FLASH_SMEM_FLOATS * 4)

__global__ __launch_bounds__(256, 2) void flash_attn_kernel()
{
    extern __shared__ float sm[];
    float* QsT = sm;
    float* KV  = sm + SM_QST;
    float* Ps  = sm + SM_QST + SM_KV;

    const int tid = threadIdx.x;
    const int tx = tid & 15, ty = tid >> 4;
    const int ltok = tid >> 2, dg = tid & 3;

    const int qb = blockIdx.x;
    const int bh = blockIdx.y;
    const int b = bh >> 4, h = bh & 15, kvh = h >> 3;

    const float* qbase = g_qkv + (size_t)(b * S_LEN + qb * 64) * QKV_N + h * HD;
    const float* kbase = g_qkv + (size_t)(b * S_LEN) * QKV_N + (NH + kvh) * HD;
    const float* vbase = g_qkv + (size_t)(b * S_LEN) * QKV_N + (NH + NKV + kvh) * HD;

#pragma unroll
    for (int i = 0; i < 8; i++) {
        int d = (dg + i * 4) * 4;
        float4 v = *(const float4*)(qbase + (size_t)ltok * QKV_N + d);
        QsT[(d + 0) * Q_PITCH + ltok] = v.x;
        QsT[(d + 1) * Q_PITCH + ltok] = v.y;
        QsT[(d + 2) * Q_PITCH + ltok] = v.z;
        QsT[(d + 3) * Q_PITCH + ltok] = v.w;
    }

    float m[4], l[4], O[4][8];
#pragma unroll
    for (int i = 0; i < 4; i++) {
        m[i] = -1e30f; l[i] = 0.0f;
#pragma unroll
        for (int j = 0; j < 8; j++) O[i][j] = 0.0f;
    }
    __syncthreads();

    for (int kt = 0; kt <= qb; kt++) {
#pragma unroll
        for (int i = 0; i < 8; i++) {
            int d = (dg + i * 4) * 4;
            float4 v = *(const float4*)(kbase + (size_t)(kt * 64 + ltok) * QKV_N + d);
            KV[(d + 0) * Q_PITCH + ltok] = v.x;
            KV[(d + 1) * Q_PITCH + ltok] = v.y;
            KV[(d + 2) * Q_PITCH + ltok] = v.z;
            KV[(d + 3) * Q_PITCH + ltok] = v.w;
        }
        __syncthreads();

        float s[4][4];
#pragma unroll
        for (int i = 0; i < 4; i++)
#pragma unroll
            for (int j = 0; j < 4; j++) s[i][j] = 0.0f;

        for (int d = 0; d < 128; d++) {
            float4 q = *(const float4*)&QsT[d * Q_PITCH + ty * 4];
            float4 k = *(const float4*)&KV[d * Q_PITCH + tx * 4];
            float qr[4] = {q.x, q.y, q.z, q.w};
            float kr[4] = {k.x, k.y, k.z, k.w};
#pragma unroll
            for (int i = 0; i < 4; i++)
#pragma unroll
                for (int j = 0; j < 4; j++)
                    s[i][j] = fmaf(qr[i], kr[j], s[i][j]);
        }

#pragma unroll
        for (int i = 0; i < 4; i++) {
            int rg = qb * 64 + ty * 4 + i;
#pragma unroll
            for (int j = 0; j < 4; j++) {
                int cg = kt * 64 + tx * 4 + j;
                s[i][j] *= SCALE;
                if (kt == qb && cg > rg) s[i][j] = -1e30f;
            }
        }

#pragma unroll
        for (int i = 0; i < 4; i++) {
            float tm = fmaxf(fmaxf(s[i][0], s[i][1]), fmaxf(s[i][2], s[i][3]));
#pragma unroll
            for (int o = 8; o >= 1; o >>= 1)
                tm = fmaxf(tm, __shfl_xor_sync(0xffffffffu, tm, o));
            float mn = fmaxf(m[i], tm);
            float alpha = __expf(m[i] - mn);
            float psum = 0.0f;
            int prow = (ty * 4 + i) * Q_PITCH + tx * 4;
#pragma unroll
            for (int j = 0; j < 4; j++) {
                float p = __expf(s[i][j] - mn);
                Ps[prow + j] = p;
                psum += p;
            }
#pragma unroll
            for (int o = 8; o >= 1; o >>= 1)
                psum += __shfl_xor_sync(0xffffffffu, psum, o);
            l[i] = l[i] * alpha + psum;
            m[i] = mn;
#pragma unroll
            for (int j = 0; j < 8; j++) O[i][j] *= alpha;
        }
        __syncthreads();

#pragma unroll
        for (int i = 0; i < 8; i++) {
            int d = (dg + i * 4) * 4;
            float4 v = *(const float4*)(vbase + (size_t)(kt * 64 + ltok) * QKV_N + d);
            *(float4*)&KV[ltok * V_PITCH + d] = v;
        }
        __syncthreads();

        for (int c = 0; c < 64; c++) {
            float pr[4];
#pragma unroll
            for (int i = 0; i < 4; i++) pr[i] = Ps[(ty * 4 + i) * Q_PITCH + c];
            float4 v0 = *(const float4*)&KV[c * V_PITCH + tx * 4];
            float4 v1 = *(const float4*)&KV[c * V_PITCH + 64 + tx * 4];
            float vr[8] = {v0.x, v0.y, v0.z, v0.w, v1.x, v1.y, v1.z, v1.w};
#pragma unroll
            for (int i = 0; i < 4; i++)
#pragma unroll
                for (int j = 0; j < 8; j++)
                    O[i][j] = fmaf(pr[i], vr[j], O[i][j]);
        }
        __syncthreads();
    }

#pragma unroll
    for (int i = 0; i < 4; i++) {
        float inv = 1.0f / l[i];
        int row = b * S_LEN + qb * 64 + ty * 4 + i;
        float4 c0, c1;
        c0.x = O[i][0] * inv; c0.y = O[i][1] * inv; c0.z = O[i][2] * inv; c0.w = O[i][3] * inv;
        c1.x = O[i][4] * inv; c1.y = O[i][5] * inv; c1.z = O[i][6] * inv; c1.w = O[i][7] * inv;
        *(float4*)&g_attn[(size_t)row * OUT_N + h * HD + tx * 4]      = c0;
        *(float4*)&g_attn[(size_t)row * OUT_N + h * HD + 64 + tx * 4] = c1;
    }
}

// ---------------- launch ----------------
extern "C" void kernel_launch(void* const* d_in, const int* in_sizes, int n_in,
                              void* d_out, int out_size)
{
    const int*   positions = nullptr;
    const float* hidden = nullptr;
    const float* Wqkv = nullptr;
    const float* bqkv = nullptr;
    const float* Wo = nullptr;
    for (int i = 0; i < n_in; i++) {
        switch (in_sizes[i]) {
            case NTOK:          positions = (const int*)d_in[i]; break;
            case NTOK * HID_D:  hidden = (const float*)d_in[i]; break;
            case HID_D * QKV_N: Wqkv = (const float*)d_in[i]; break;
            case QKV_N:         bqkv = (const float*)d_in[i]; break;
            case OUT_N * HID_D: Wo = (const float*)d_in[i]; break;
        }
    }

    float* qkv;   cudaGetSymbolAddress((void**)&qkv,   g_qkv);
    float* attn;  cudaGetSymbolAddress((void**)&attn,  g_attn);
    float* wqkvT; cudaGetSymbolAddress((void**)&wqkvT, g_wqkvT);
    float* woT;   cudaGetSymbolAddress((void**)&woT,   g_woT);
    float* out = (float*)d_out;

    cudaFuncSetAttribute(flash_attn_kernel,
                         cudaFuncAttributeMaxDynamicSharedMemorySize, FLASH_SMEM_BYTES);

    // 0. RoPE table + weight transposes (Bt layouts for K-contiguous loads)
    rope_table_kernel<<<(S_LEN * 64 + 255) / 256, 256>>>();
    {
        dim3 blk(32, 8);
        transpose_kernel<<<dim3(QKV_N / 32, HID_D / 32), blk>>>(Wqkv, wqkvT, HID_D, QKV_N);
        transpose_kernel<<<dim3(HID_D / 32, OUT_N / 32), blk>>>(Wo, woT, OUT_N, HID_D);
    }

    // 1. QKV projection (+bias), fp16 tensor cores
    {
        dim3 grid(QKV_N / 128, NTOK / 128);
        gemm_f16_kernel<true><<<grid, 256>>>(hidden, wqkvT, bqkv, qkv, NTOK, QKV_N, HID_D);
    }

    // 2. RoPE apply
    {
        size_t total = (size_t)NTOK * (NH + NKV) * 64;
        rope_apply_kernel<<<(unsigned)((total + 255) / 256), 256>>>(positions);
    }

    // 3. Flash attention
    {
        dim3 grid(S_LEN / 64, BATCH * NH);
        flash_attn_kernel<<<grid, 256, FLASH_SMEM_BYTES>>>();
    }

    // 4. Output projection, fp16 tensor cores
    {
        dim3 grid(HID_D / 128, NTOK / 128);
        gemm_f16_kernel<false><<<grid, 256>>>(attn, woT, nullptr, out, NTOK, HID_D, OUT_N);
    }
}

// round 10
// speedup vs baseline: 1.9038x; 1.4773x over previous
#include <cuda_runtime.h>
#include <cuda_fp16.h>
#include <cstdint>
#include <math.h>

#define BATCH  2
#define S_LEN  2048
#define HID_D  2048
#define NH     16
#define NKV    2
#define HD     128
#define QKV_N  ((NH + 2*NKV) * HD)   // 2560
#define NTOK   (BATCH * S_LEN)       // 4096
#define OUT_N  (NH * HD)             // 2048
#define SCALE  0.08838834764831843f  // 128^-0.5

// ---------------- scratch (device globals; no allocation allowed) ----------------
__device__ __align__(16) float  g_qkv[(size_t)NTOK * QKV_N];       // fp32 (rope + flash)
__device__ __align__(16) float  g_cs[(size_t)S_LEN * HD];
__device__ __align__(16) __half g_hidden_h[(size_t)NTOK * HID_D];  // half A for GEMM1
__device__ __align__(16) __half g_wqkvT_h[(size_t)QKV_N * HID_D];  // half Wqkv^T [N][K]
__device__ __align__(16) __half g_woT_h[(size_t)HID_D * OUT_N];    // half Wo^T   [N][K]
__device__ __align__(16) __half g_attnh[(size_t)NTOK * OUT_N];     // half attn out (A for GEMM2)

// ---------------- RoPE cos/sin table (fp64 for angle accuracy) ----------------
__global__ void rope_table_kernel() {
    int idx = blockIdx.x * blockDim.x + threadIdx.x;
    if (idx >= S_LEN * 64) return;
    int s = idx >> 6, i = idx & 63;
    double inv = pow(1000000.0, -(double)i / 64.0);
    double ang = (double)s * inv;
    g_cs[s * HD + i]      = (float)cos(ang);
    g_cs[s * HD + 64 + i] = (float)sin(ang);
}

// ---------------- RoPE apply (q: 16 heads, k: 2 heads) ----------------
__global__ void rope_apply_kernel(const int* __restrict__ positions) {
    size_t idx = (size_t)blockIdx.x * blockDim.x + threadIdx.x;
    const size_t total = (size_t)NTOK * (NH + NKV) * 64;
    if (idx >= total) return;
    int i    = idx & 63;
    size_t r = idx >> 6;
    int head = (int)(r % (NH + NKV));
    int t    = (int)(r / (NH + NKV));
    int pos  = positions[t];
    float c  = g_cs[pos * HD + i];
    float sn = g_cs[pos * HD + 64 + i];
    int off  = (head < NH) ? head * HD : (NH * HD + (head - NH) * HD);
    float* p = g_qkv + (size_t)t * QKV_N + off;
    float x1 = p[i], x2 = p[i + 64];
    p[i]      = x1 * c - x2 * sn;
    p[i + 64] = x2 * c + x1 * sn;
}

// ---------------- fp32 -> fp16 convert ----------------
__global__ void f2h_kernel(const float* __restrict__ in, __half* __restrict__ out, int n4) {
    int i = blockIdx.x * blockDim.x + threadIdx.x;
    if (i >= n4) return;
    float4 v = ((const float4*)in)[i];
    __half2 h0 = __floats2half2_rn(v.x, v.y);
    __half2 h1 = __floats2half2_rn(v.z, v.w);
    ((uint2*)out)[i] = make_uint2(*(unsigned*)&h0, *(unsigned*)&h1);
}

// ---------------- weight transpose + convert: out_h[N][K] = in[K][N] ----------------
__global__ void transpose_h_kernel(const float* __restrict__ in, __half* __restrict__ out,
                                   int rows, int cols) {
    __shared__ float t[32][33];
    int x = blockIdx.x * 32 + threadIdx.x;
    int y = blockIdx.y * 32 + threadIdx.y;
#pragma unroll
    for (int j = 0; j < 32; j += 8)
        t[threadIdx.y + j][threadIdx.x] = in[(size_t)(y + j) * cols + x];
    __syncthreads();
    x = blockIdx.y * 32 + threadIdx.x;
    y = blockIdx.x * 32 + threadIdx.y;
#pragma unroll
    for (int j = 0; j < 32; j += 8)
        out[(size_t)(y + j) * rows + x] = __float2half(t[threadIdx.x][threadIdx.y + j]);
}

// ============ fp16 mma GEMM, cp.async 4-stage + ldmatrix ============
// C[M,N] = A_h[M,K] @ Bt_h[N,K]^T (+bias). 128x128 CTA tile, 8 warps (2x4),
// warp tile 64x32, mma.m16n8k16, fp32 accum. K-chunk 32 halves (64B/row).
// Swizzle: 16B-chunk c of row r stored at c ^ ((r>>1)&3)  -> conflict-free
// for both cp.async stores and both LDSM phases.

__device__ __forceinline__ uint32_t smem_u32(const void* p) {
    uint32_t a;
    asm("{ .reg .u64 t; cvta.to.shared.u64 t, %1; cvt.u32.u64 %0, t; }" : "=r"(a) : "l"(p));
    return a;
}

#define CP16(d, s) \
    asm volatile("cp.async.cg.shared.global [%0], [%1], 16;" :: "r"(d), "l"(s))
#define CP_COMMIT() asm volatile("cp.async.commit_group;" ::: "memory")
#define CP_WAIT2()  asm volatile("cp.async.wait_group 2;" ::: "memory")

#define LDSM4(r0, r1, r2, r3, a)                                              \
    asm volatile("ldmatrix.sync.aligned.m8n8.x4.shared.b16 {%0,%1,%2,%3}, [%4];" \
                 : "=r"(r0), "=r"(r1), "=r"(r2), "=r"(r3) : "r"(a))

#define MMA_F16(d, a, b)                                                      \
    asm volatile("mma.sync.aligned.m16n8k16.row.col.f32.f16.f16.f32 "         \
                 "{%0,%1,%2,%3}, {%4,%5,%6,%7}, {%8,%9}, {%0,%1,%2,%3};"      \
                 : "+f"(d[0]), "+f"(d[1]), "+f"(d[2]), "+f"(d[3])             \
                 : "r"(a[0]), "r"(a[1]), "r"(a[2]), "r"(a[3]),                \
                   "r"(b[0]), "r"(b[1]))

#define GSTAGE  16384              // 8KB A + 8KB B per stage
#define GSMEM   (4 * GSTAGE)       // 64 KB

template <bool BIAS>
__global__ __launch_bounds__(256, 2) void gemm_h_kernel(
    const __half* __restrict__ A, const __half* __restrict__ Bt,
    const float* __restrict__ bias, float* __restrict__ C,
    int M, int N, int K)
{
    extern __shared__ char gsm[];
    const uint32_t sb = smem_u32(gsm);
    const int tid = threadIdx.x;
    const int lane = tid & 31, w = tid >> 5;
    const int bm = blockIdx.y * 128, bn = blockIdx.x * 128;
    const int wm = (w >> 2) * 64, wn = (w & 3) * 32;
    const int grp = lane >> 2, tig = lane & 3;

    // ---- cp.async fill mapping: thread t -> tile row r = t>>1, chunks c0, c0+1 ----
    const int fr = tid >> 1;
    const int fc0 = (tid & 1) * 2;
    const __half* Ap = A  + (size_t)(bm + fr) * K + fc0 * 8;
    const __half* Bp = Bt + (size_t)(bn + fr) * K + fc0 * 8;
    const uint32_t fsw0 = (uint32_t)(fr * 64 + (((fc0 + 0) ^ ((fr >> 1) & 3)) << 4));
    const uint32_t fsw1 = (uint32_t)(fr * 64 + (((fc0 + 1) ^ ((fr >> 1) & 3)) << 4));

    // ---- ldmatrix address offsets (per-thread constants) ----
    uint32_t a_off[4][2], b_off[2][2];
    {
        const int j = lane >> 3, lr = lane & 7;
#pragma unroll
        for (int mt = 0; mt < 4; mt++)
#pragma unroll
            for (int ks = 0; ks < 2; ks++) {
                int row = wm + mt * 16 + (j & 1) * 8 + lr;
                int kc  = ks * 2 + (j >> 1);
                a_off[mt][ks] = (uint32_t)(row * 64 + ((kc ^ ((row >> 1) & 3)) << 4));
            }
#pragma unroll
        for (int np = 0; np < 2; np++)
#pragma unroll
            for (int ks = 0; ks < 2; ks++) {
                int nt  = np * 2 + (j >> 1);
                int row = wn + nt * 8 + lr;
                int kc  = ks * 2 + (j & 1);
                b_off[np][ks] = (uint32_t)(8192 + row * 64 + ((kc ^ ((row >> 1) & 3)) << 4));
            }
    }

    float acc[4][4][4];
#pragma unroll
    for (int mt = 0; mt < 4; mt++)
#pragma unroll
        for (int nt = 0; nt < 4; nt++)
#pragma unroll
            for (int r = 0; r < 4; r++) acc[mt][nt][r] = 0.0f;

    const int nk = K >> 5;

    auto load_stage = [&](int kt, int st) {
        uint32_t s = sb + st * GSTAGE;
        const __half* ap = Ap + kt * 32;
        const __half* bp = Bp + kt * 32;
        CP16(s + fsw0,        ap);
        CP16(s + fsw1,        ap + 8);
        CP16(s + 8192 + fsw0, bp);
        CP16(s + 8192 + fsw1, bp + 8);
    };

    // prologue: stages 0..2
#pragma unroll
    for (int s = 0; s < 3; s++) { load_stage(s, s); CP_COMMIT(); }

    for (int kt = 0; kt < nk; kt++) {
        CP_WAIT2();
        __syncthreads();
        const int st = kt & 3;
        if (kt + 3 < nk) load_stage(kt + 3, (kt + 3) & 3);
        CP_COMMIT();

        const uint32_t s = sb + st * GSTAGE;
#pragma unroll
        for (int ks = 0; ks < 2; ks++) {
            unsigned af[4][4], bf[4][2];
#pragma unroll
            for (int mt = 0; mt < 4; mt++)
                LDSM4(af[mt][0], af[mt][1], af[mt][2], af[mt][3], s + a_off[mt][ks]);
#pragma unroll
            for (int np = 0; np < 2; np++)
                LDSM4(bf[np * 2][0], bf[np * 2][1], bf[np * 2 + 1][0], bf[np * 2 + 1][1],
                      s + b_off[np][ks]);
#pragma unroll
            for (int mt = 0; mt < 4; mt++)
#pragma unroll
                for (int nt = 0; nt < 4; nt++)
                    MMA_F16(acc[mt][nt], af[mt], bf[nt]);
        }
    }

    // epilogue: rows (bm+wm+mt*16+grp, +8), cols (bn+wn+nt*8+2*tig, +1)
#pragma unroll
    for (int nt = 0; nt < 4; nt++) {
        int c = bn + wn + nt * 8 + tig * 2;
        float b0 = 0.0f, b1 = 0.0f;
        if (BIAS) { b0 = bias[c]; b1 = bias[c + 1]; }
#pragma unroll
        for (int mt = 0; mt < 4; mt++) {
            int r = bm + wm + mt * 16 + grp;
            float2 v0, v1;
            v0.x = acc[mt][nt][0] + b0; v0.y = acc[mt][nt][1] + b1;
            v1.x = acc[mt][nt][2] + b0; v1.y = acc[mt][nt][3] + b1;
            *(float2*)&C[(size_t)r * N + c]       = v0;
            *(float2*)&C[(size_t)(r + 8) * N + c] = v1;
        }
    }
}

// ---------------- Flash attention: BQ=64, BK=64, causal, GQA (rep=8) ----------------
#define Q_PITCH 68
#define V_PITCH 132
#define SM_QST   (128 * Q_PITCH)
#define SM_KV    (128 * Q_PITCH)
#define SM_PS    (64 * Q_PITCH)
#define FLASH_SMEM_FLOATS (SM_QST + SM_KV + SM_PS)
#define FLASH_SMEM_BYTES  (FLASH_SMEM_FLOATS * 4)

__global__ __launch_bounds__(256, 2) void flash_attn_kernel()
{
    extern __shared__ float sm[];
    float* QsT = sm;
    float* KV  = sm + SM_QST;
    float* Ps  = sm + SM_QST + SM_KV;

    const int tid = threadIdx.x;
    const int tx = tid & 15, ty = tid >> 4;
    const int ltok = tid >> 2, dg = tid & 3;

    const int qb = blockIdx.x;
    const int bh = blockIdx.y;
    const int b = bh >> 4, h = bh & 15, kvh = h >> 3;

    const float* qbase = g_qkv + (size_t)(b * S_LEN + qb * 64) * QKV_N + h * HD;
    const float* kbase = g_qkv + (size_t)(b * S_LEN) * QKV_N + (NH + kvh) * HD;
    const float* vbase = g_qkv + (size_t)(b * S_LEN) * QKV_N + (NH + NKV + kvh) * HD;

#pragma unroll
    for (int i = 0; i < 8; i++) {
        int d = (dg + i * 4) * 4;
        float4 v = *(const float4*)(qbase + (size_t)ltok * QKV_N + d);
        QsT[(d + 0) * Q_PITCH + ltok] = v.x;
        QsT[(d + 1) * Q_PITCH + ltok] = v.y;
        QsT[(d + 2) * Q_PITCH + ltok] = v.z;
        QsT[(d + 3) * Q_PITCH + ltok] = v.w;
    }

    float m[4], l[4], O[4][8];
#pragma unroll
    for (int i = 0; i < 4; i++) {
        m[i] = -1e30f; l[i] = 0.0f;
#pragma unroll
        for (int j = 0; j < 8; j++) O[i][j] = 0.0f;
    }
    __syncthreads();

    for (int kt = 0; kt <= qb; kt++) {
#pragma unroll
        for (int i = 0; i < 8; i++) {
            int d = (dg + i * 4) * 4;
            float4 v = *(const float4*)(kbase + (size_t)(kt * 64 + ltok) * QKV_N + d);
            KV[(d + 0) * Q_PITCH + ltok] = v.x;
            KV[(d + 1) * Q_PITCH + ltok] = v.y;
            KV[(d + 2) * Q_PITCH + ltok] = v.z;
            KV[(d + 3) * Q_PITCH + ltok] = v.w;
        }
        __syncthreads();

        float s[4][4];
#pragma unroll
        for (int i = 0; i < 4; i++)
#pragma unroll
            for (int j = 0; j < 4; j++) s[i][j] = 0.0f;

        for (int d = 0; d < 128; d++) {
            float4 q = *(const float4*)&QsT[d * Q_PITCH + ty * 4];
            float4 k = *(const float4*)&KV[d * Q_PITCH + tx * 4];
            float qr[4] = {q.x, q.y, q.z, q.w};
            float kr[4] = {k.x, k.y, k.z, k.w};
#pragma unroll
            for (int i = 0; i < 4; i++)
#pragma unroll
                for (int j = 0; j < 4; j++)
                    s[i][j] = fmaf(qr[i], kr[j], s[i][j]);
        }

#pragma unroll
        for (int i = 0; i < 4; i++) {
            int rg = qb * 64 + ty * 4 + i;
#pragma unroll
            for (int j = 0; j < 4; j++) {
                int cg = kt * 64 + tx * 4 + j;
                s[i][j] *= SCALE;
                if (kt == qb && cg > rg) s[i][j] = -1e30f;
            }
        }

#pragma unroll
        for (int i = 0; i < 4; i++) {
            float tm = fmaxf(fmaxf(s[i][0], s[i][1]), fmaxf(s[i][2], s[i][3]));
#pragma unroll
            for (int o = 8; o >= 1; o >>= 1)
                tm = fmaxf(tm, __shfl_xor_sync(0xffffffffu, tm, o));
            float mn = fmaxf(m[i], tm);
            float alpha = __expf(m[i] - mn);
            float psum = 0.0f;
            int prow = (ty * 4 + i) * Q_PITCH + tx * 4;
#pragma unroll
            for (int j = 0; j < 4; j++) {
                float p = __expf(s[i][j] - mn);
                Ps[prow + j] = p;
                psum += p;
            }
#pragma unroll
            for (int o = 8; o >= 1; o >>= 1)
                psum += __shfl_xor_sync(0xffffffffu, psum, o);
            l[i] = l[i] * alpha + psum;
            m[i] = mn;
#pragma unroll
            for (int j = 0; j < 8; j++) O[i][j] *= alpha;
        }
        __syncthreads();

#pragma unroll
        for (int i = 0; i < 8; i++) {
            int d = (dg + i * 4) * 4;
            float4 v = *(const float4*)(vbase + (size_t)(kt * 64 + ltok) * QKV_N + d);
            *(float4*)&KV[ltok * V_PITCH + d] = v;
        }
        __syncthreads();

        for (int c = 0; c < 64; c++) {
            float pr[4];
#pragma unroll
            for (int i = 0; i < 4; i++) pr[i] = Ps[(ty * 4 + i) * Q_PITCH + c];
            float4 v0 = *(const float4*)&KV[c * V_PITCH + tx * 4];
            float4 v1 = *(const float4*)&KV[c * V_PITCH + 64 + tx * 4];
            float vr[8] = {v0.x, v0.y, v0.z, v0.w, v1.x, v1.y, v1.z, v1.w};
#pragma unroll
            for (int i = 0; i < 4; i++)
#pragma unroll
                for (int j = 0; j < 8; j++)
                    O[i][j] = fmaf(pr[i], vr[j], O[i][j]);
        }
        __syncthreads();
    }

    // ---- epilogue: O /= l, write HALF to g_attnh (input of O-proj GEMM) ----
#pragma unroll
    for (int i = 0; i < 4; i++) {
        float inv = 1.0f / l[i];
        int row = b * S_LEN + qb * 64 + ty * 4 + i;
        __half2 h0 = __floats2half2_rn(O[i][0] * inv, O[i][1] * inv);
        __half2 h1 = __floats2half2_rn(O[i][2] * inv, O[i][3] * inv);
        __half2 h2 = __floats2half2_rn(O[i][4] * inv, O[i][5] * inv);
        __half2 h3 = __floats2half2_rn(O[i][6] * inv, O[i][7] * inv);
        *(uint2*)&g_attnh[(size_t)row * OUT_N + h * HD + tx * 4] =
            make_uint2(*(unsigned*)&h0, *(unsigned*)&h1);
        *(uint2*)&g_attnh[(size_t)row * OUT_N + h * HD + 64 + tx * 4] =
            make_uint2(*(unsigned*)&h2, *(unsigned*)&h3);
    }
}

// ---------------- launch ----------------
extern "C" void kernel_launch(void* const* d_in, const int* in_sizes, int n_in,
                              void* d_out, int out_size)
{
    const int*   positions = nullptr;
    const float* hidden = nullptr;
    const float* Wqkv = nullptr;
    const float* bqkv = nullptr;
    const float* Wo = nullptr;
    for (int i = 0; i < n_in; i++) {
        switch (in_sizes[i]) {
            case NTOK:          positions = (const int*)d_in[i]; break;
            case NTOK * HID_D:  hidden = (const float*)d_in[i]; break;
            case HID_D * QKV_N: Wqkv = (const float*)d_in[i]; break;
            case QKV_N:         bqkv = (const float*)d_in[i]; break;
            case OUT_N * HID_D: Wo = (const float*)d_in[i]; break;
        }
    }

    float*  qkv;      cudaGetSymbolAddress((void**)&qkv,      g_qkv);
    __half* hidden_h; cudaGetSymbolAddress((void**)&hidden_h, g_hidden_h);
    __half* wqkvT_h;  cudaGetSymbolAddress((void**)&wqkvT_h,  g_wqkvT_h);
    __half* woT_h;    cudaGetSymbolAddress((void**)&woT_h,    g_woT_h);
    __half* attnh;    cudaGetSymbolAddress((void**)&attnh,    g_attnh);
    float* out = (float*)d_out;

    cudaFuncSetAttribute(gemm_h_kernel<true>,
                         cudaFuncAttributeMaxDynamicSharedMemorySize, GSMEM);
    cudaFuncSetAttribute(gemm_h_kernel<false>,
                         cudaFuncAttributeMaxDynamicSharedMemorySize, GSMEM);
    cudaFuncSetAttribute(flash_attn_kernel,
                         cudaFuncAttributeMaxDynamicSharedMemorySize, FLASH_SMEM_BYTES);

    // 0. RoPE table + operand conversion
    rope_table_kernel<<<(S_LEN * 64 + 255) / 256, 256>>>();
    f2h_kernel<<<(NTOK * HID_D / 4 + 255) / 256, 256>>>(hidden, hidden_h, NTOK * HID_D / 4);
    {
        dim3 blk(32, 8);
        transpose_h_kernel<<<dim3(QKV_N / 32, HID_D / 32), blk>>>(Wqkv, wqkvT_h, HID_D, QKV_N);
        transpose_h_kernel<<<dim3(HID_D / 32, OUT_N / 32), blk>>>(Wo, woT_h, OUT_N, HID_D);
    }

    // 1. QKV projection (+bias), fp16 mma + cp.async pipeline
    {
        dim3 grid(QKV_N / 128, NTOK / 128);
        gemm_h_kernel<true><<<grid, 256, GSMEM>>>(hidden_h, wqkvT_h, bqkv, qkv,
                                                  NTOK, QKV_N, HID_D);
    }

    // 2. RoPE apply
    {
        size_t total = (size_t)NTOK * (NH + NKV) * 64;
        rope_apply_kernel<<<(unsigned)((total + 255) / 256), 256>>>(positions);
    }

    // 3. Flash attention (writes half output)
    {
        dim3 grid(S_LEN / 64, BATCH * NH);
        flash_attn_kernel<<<grid, 256, FLASH_SMEM_BYTES>>>();
    }

    // 4. Output projection, fp16 mma + cp.async pipeline
    {
        dim3 grid(HID_D / 128, NTOK / 128);
        gemm_h_kernel<false><<<grid, 256, GSMEM>>>(attnh, woT_h, nullptr, out,
                                                   NTOK, HID_D, OUT_N);
    }
}

// round 11
// speedup vs baseline: 4.7446x; 2.4921x over previous
#include <cuda_runtime.h>
#include <cuda_fp16.h>
#include <cstdint>
#include <math.h>

#define BATCH  2
#define S_LEN  2048
#define HID_D  2048
#define NH     16
#define NKV    2
#define HD     128
#define QKV_N  ((NH + 2*NKV) * HD)   // 2560
#define NTOK   (BATCH * S_LEN)       // 4096
#define OUT_N  (NH * HD)             // 2048
#define SCALE  0.08838834764831843f  // 128^-0.5

// ---------------- scratch (device globals; no allocation allowed) ----------------
__device__ __align__(16) float  g_qkv[(size_t)NTOK * QKV_N];       // fp32 GEMM1 out
__device__ __align__(16) float  g_cs[(size_t)S_LEN * HD];
__device__ __align__(16) __half g_hidden_h[(size_t)NTOK * HID_D];
__device__ __align__(16) __half g_wqkvT_h[(size_t)QKV_N * HID_D];
__device__ __align__(16) __half g_woT_h[(size_t)HID_D * OUT_N];
__device__ __align__(16) __half g_attnh[(size_t)NTOK * OUT_N];
__device__ __align__(16) __half g_qh[(size_t)BATCH * NH * S_LEN * HD];   // roped Q, per-head
__device__ __align__(16) __half g_kh[(size_t)BATCH * NKV * S_LEN * HD];  // roped K, per-head
__device__ __align__(16) __half g_vh[(size_t)BATCH * NKV * S_LEN * HD];  // V, per-head

// ---------------- common PTX helpers ----------------
__device__ __forceinline__ uint32_t smem_u32(const void* p) {
    uint32_t a;
    asm("{ .reg .u64 t; cvta.to.shared.u64 t, %1; cvt.u32.u64 %0, t; }" : "=r"(a) : "l"(p));
    return a;
}
#define CP16(d, s) \
    asm volatile("cp.async.cg.shared.global [%0], [%1], 16;" :: "r"(d), "l"(s))
#define CP_COMMIT() asm volatile("cp.async.commit_group;" ::: "memory")
#define LDSM4(r0, r1, r2, r3, a)                                              \
    asm volatile("ldmatrix.sync.aligned.m8n8.x4.shared.b16 {%0,%1,%2,%3}, [%4];" \
                 : "=r"(r0), "=r"(r1), "=r"(r2), "=r"(r3) : "r"(a))
#define LDSM4T(r0, r1, r2, r3, a)                                             \
    asm volatile("ldmatrix.sync.aligned.m8n8.x4.trans.shared.b16 {%0,%1,%2,%3}, [%4];" \
                 : "=r"(r0), "=r"(r1), "=r"(r2), "=r"(r3) : "r"(a))
#define MMA_F16(d, a, b)                                                      \
    asm volatile("mma.sync.aligned.m16n8k16.row.col.f32.f16.f16.f32 "         \
                 "{%0,%1,%2,%3}, {%4,%5,%6,%7}, {%8,%9}, {%0,%1,%2,%3};"      \
                 : "+f"(d[0]), "+f"(d[1]), "+f"(d[2]), "+f"(d[3])             \
                 : "r"(a[0]), "r"(a[1]), "r"(a[2]), "r"(a[3]),                \
                   "r"(b[0]), "r"(b[1]))

// ---------------- RoPE cos/sin table (fp64 for angle accuracy) ----------------
__global__ void rope_table_kernel() {
    int idx = blockIdx.x * blockDim.x + threadIdx.x;
    if (idx >= S_LEN * 64) return;
    int s = idx >> 6, i = idx & 63;
    double inv = pow(1000000.0, -(double)i / 64.0);
    double ang = (double)s * inv;
    g_cs[s * HD + i]      = (float)cos(ang);
    g_cs[s * HD + 64 + i] = (float)sin(ang);
}

// ------- RoPE + convert to per-head half layout (q 16h, k 2h rope; v 2h copy) -------
__global__ void rope_h_kernel(const int* __restrict__ positions) {
    size_t idx = (size_t)blockIdx.x * blockDim.x + threadIdx.x;
    const size_t total = (size_t)NTOK * 20 * 64;   // 18 rope heads + 2 v heads
    if (idx >= total) return;
    int i    = idx & 63;
    size_t r = idx >> 6;
    int head = (int)(r % 20);
    int t    = (int)(r / 20);
    int b = t / S_LEN, s = t % S_LEN;
    int pos  = positions[t];
    if (head < NH + NKV) {
        float c  = g_cs[pos * HD + i];
        float sn = g_cs[pos * HD + 64 + i];
        const float* p;
        __half* out;
        if (head < NH) {
            p   = g_qkv + (size_t)t * QKV_N + head * HD;
            out = g_qh + ((size_t)(b * NH + head) * S_LEN + s) * HD;
        } else {
            int kvh = head - NH;
            p   = g_qkv + (size_t)t * QKV_N + NH * HD + kvh * HD;
            out = g_kh + ((size_t)(b * NKV + kvh) * S_LEN + s) * HD;
        }
        float x1 = p[i], x2 = p[i + 64];
        out[i]      = __float2half(x1 * c - x2 * sn);
        out[i + 64] = __float2half(x2 * c + x1 * sn);
    } else {
        int kvh = head - NH - NKV;
        const float* p = g_qkv + (size_t)t * QKV_N + (NH + NKV) * HD + kvh * HD;
        __half* out = g_vh + ((size_t)(b * NKV + kvh) * S_LEN + s) * HD;
        out[i]      = __float2half(p[i]);
        out[i + 64] = __float2half(p[i + 64]);
    }
}

// ---------------- fp32 -> fp16 convert ----------------
__global__ void f2h_kernel(const float* __restrict__ in, __half* __restrict__ out, int n4) {
    int i = blockIdx.x * blockDim.x + threadIdx.x;
    if (i >= n4) return;
    float4 v = ((const float4*)in)[i];
    __half2 h0 = __floats2half2_rn(v.x, v.y);
    __half2 h1 = __floats2half2_rn(v.z, v.w);
    ((uint2*)out)[i] = make_uint2(*(unsigned*)&h0, *(unsigned*)&h1);
}

// ---------------- weight transpose + convert: out_h[N][K] = in[K][N] ----------------
__global__ void transpose_h_kernel(const float* __restrict__ in, __half* __restrict__ out,
                                   int rows, int cols) {
    __shared__ float t[32][33];
    int x = blockIdx.x * 32 + threadIdx.x;
    int y = blockIdx.y * 32 + threadIdx.y;
#pragma unroll
    for (int j = 0; j < 32; j += 8)
        t[threadIdx.y + j][threadIdx.x] = in[(size_t)(y + j) * cols + x];
    __syncthreads();
    x = blockIdx.y * 32 + threadIdx.x;
    y = blockIdx.x * 32 + threadIdx.y;
#pragma unroll
    for (int j = 0; j < 32; j += 8)
        out[(size_t)(y + j) * rows + x] = __float2half(t[threadIdx.x][threadIdx.y + j]);
}

// ============ fp16 mma GEMM, cp.async 4-stage + ldmatrix (unchanged from R10) ============
#define GSTAGE  16384
#define GSMEM   (4 * GSTAGE)

template <bool BIAS>
__global__ __launch_bounds__(256, 2) void gemm_h_kernel(
    const __half* __restrict__ A, const __half* __restrict__ Bt,
    const float* __restrict__ bias, float* __restrict__ C,
    int M, int N, int K)
{
    extern __shared__ char gsm[];
    const uint32_t sb = smem_u32(gsm);
    const int tid = threadIdx.x;
    const int lane = tid & 31, w = tid >> 5;
    const int bm = blockIdx.y * 128, bn = blockIdx.x * 128;
    const int wm = (w >> 2) * 64, wn = (w & 3) * 32;
    const int grp = lane >> 2, tig = lane & 3;

    const int fr = tid >> 1;
    const int fc0 = (tid & 1) * 2;
    const __half* Ap = A  + (size_t)(bm + fr) * K + fc0 * 8;
    const __half* Bp = Bt + (size_t)(bn + fr) * K + fc0 * 8;
    const uint32_t fsw0 = (uint32_t)(fr * 64 + (((fc0 + 0) ^ ((fr >> 1) & 3)) << 4));
    const uint32_t fsw1 = (uint32_t)(fr * 64 + (((fc0 + 1) ^ ((fr >> 1) & 3)) << 4));

    uint32_t a_off[4][2], b_off[2][2];
    {
        const int j = lane >> 3, lr = lane & 7;
#pragma unroll
        for (int mt = 0; mt < 4; mt++)
#pragma unroll
            for (int ks = 0; ks < 2; ks++) {
                int row = wm + mt * 16 + (j & 1) * 8 + lr;
                int kc  = ks * 2 + (j >> 1);
                a_off[mt][ks] = (uint32_t)(row * 64 + ((kc ^ ((row >> 1) & 3)) << 4));
            }
#pragma unroll
        for (int np = 0; np < 2; np++)
#pragma unroll
            for (int ks = 0; ks < 2; ks++) {
                int nt  = np * 2 + (j >> 1);
                int row = wn + nt * 8 + lr;
                int kc  = ks * 2 + (j & 1);
                b_off[np][ks] = (uint32_t)(8192 + row * 64 + ((kc ^ ((row >> 1) & 3)) << 4));
            }
    }

    float acc[4][4][4];
#pragma unroll
    for (int mt = 0; mt < 4; mt++)
#pragma unroll
        for (int nt = 0; nt < 4; nt++)
#pragma unroll
            for (int r = 0; r < 4; r++) acc[mt][nt][r] = 0.0f;

    const int nk = K >> 5;

    auto load_stage = [&](int kt, int st) {
        uint32_t s = sb + st * GSTAGE;
        const __half* ap = Ap + kt * 32;
        const __half* bp = Bp + kt * 32;
        CP16(s + fsw0,        ap);
        CP16(s + fsw1,        ap + 8);
        CP16(s + 8192 + fsw0, bp);
        CP16(s + 8192 + fsw1, bp + 8);
    };

#pragma unroll
    for (int s = 0; s < 3; s++) { load_stage(s, s); CP_COMMIT(); }

    for (int kt = 0; kt < nk; kt++) {
        asm volatile("cp.async.wait_group 2;" ::: "memory");
        __syncthreads();
        const int st = kt & 3;
        if (kt + 3 < nk) load_stage(kt + 3, (kt + 3) & 3);
        CP_COMMIT();

        const uint32_t s = sb + st * GSTAGE;
#pragma unroll
        for (int ks = 0; ks < 2; ks++) {
            unsigned af[4][4], bf[4][2];
#pragma unroll
            for (int mt = 0; mt < 4; mt++)
                LDSM4(af[mt][0], af[mt][1], af[mt][2], af[mt][3], s + a_off[mt][ks]);
#pragma unroll
            for (int np = 0; np < 2; np++)
                LDSM4(bf[np * 2][0], bf[np * 2][1], bf[np * 2 + 1][0], bf[np * 2 + 1][1],
                      s + b_off[np][ks]);
#pragma unroll
            for (int mt = 0; mt < 4; mt++)
#pragma unroll
                for (int nt = 0; nt < 4; nt++)
                    MMA_F16(acc[mt][nt], af[mt], bf[nt]);
        }
    }

#pragma unroll
    for (int nt = 0; nt < 4; nt++) {
        int c = bn + wn + nt * 8 + tig * 2;
        float b0 = 0.0f, b1 = 0.0f;
        if (BIAS) { b0 = bias[c]; b1 = bias[c + 1]; }
#pragma unroll
        for (int mt = 0; mt < 4; mt++) {
            int r = bm + wm + mt * 16 + grp;
            float2 v0, v1;
            v0.x = acc[mt][nt][0] + b0; v0.y = acc[mt][nt][1] + b1;
            v1.x = acc[mt][nt][2] + b0; v1.y = acc[mt][nt][3] + b1;
            *(float2*)&C[(size_t)r * N + c]       = v0;
            *(float2*)&C[(size_t)(r + 8) * N + c] = v1;
        }
    }
}

// ============ Tensor-core flash attention: BQ=64, BK=64, 4 warps ============
// smem: Q 16KB @0 | stage0: K@16384 V@32768 | stage1: K@49152 V@65536  (80KB)
// Row = 128 halfs = 256B = 16 chunks of 16B; chunk c of row r at (c ^ (r&7)).
#define FSMEM 81920

__global__ __launch_bounds__(128) void flash_mma_kernel()
{
    extern __shared__ char fsm[];
    const uint32_t sb = smem_u32(fsm);
    const int tid = threadIdx.x, lane = tid & 31, w = tid >> 5;
    const int grp = lane >> 2, tig = lane & 3;
    const int qb = blockIdx.x, bh = blockIdx.y;
    const int b = bh >> 4, h = bh & 15, kvh = h >> 3;

    const __half* qptr = g_qh + ((size_t)(b * NH + h) * S_LEN + qb * 64) * HD;
    const __half* kptr = g_kh + (size_t)(b * NKV + kvh) * S_LEN * HD;
    const __half* vptr = g_vh + (size_t)(b * NKV + kvh) * S_LEN * HD;

    const int fr = tid >> 1, fc0 = (tid & 1) * 8;

    // ---- prologue: async-load Q tile, then KV tile 0 ----
    {
        const __half* src = qptr + (size_t)fr * HD + fc0 * 8;
        uint32_t dst = sb + fr * 256;
#pragma unroll
        for (int j = 0; j < 8; j++) {
            int c = fc0 + j;
            CP16(dst + ((c ^ (fr & 7)) << 4), src + j * 8);
        }
    }
    CP_COMMIT();

    auto fill_kv = [&](int kt, int st) {
        uint32_t kb = sb + 16384 + st * 32768;
        const __half* ks = kptr + (size_t)(kt * 64 + fr) * HD + fc0 * 8;
        const __half* vs = vptr + (size_t)(kt * 64 + fr) * HD + fc0 * 8;
        uint32_t rb = fr * 256;
#pragma unroll
        for (int j = 0; j < 8; j++) {
            int c = fc0 + j;
            uint32_t sw = rb + ((c ^ (fr & 7)) << 4);
            CP16(kb + sw,         ks + j * 8);
            CP16(kb + 16384 + sw, vs + j * 8);
        }
    };
    fill_kv(0, 0);
    CP_COMMIT();

    // ---- Q fragments into registers (8 k16-steps, kept for whole loop) ----
    asm volatile("cp.async.wait_group 1;" ::: "memory");
    __syncthreads();
    unsigned qf[8][4];
    {
        int row = w * 16 + ((lane >> 3) & 1) * 8 + (lane & 7);
        uint32_t rb = sb + row * 256;
#pragma unroll
        for (int j = 0; j < 8; j++) {
            int chunk = 2 * j + (lane >> 4);
            LDSM4(qf[j][0], qf[j][1], qf[j][2], qf[j][3],
                  rb + ((chunk ^ (row & 7)) << 4));
        }
    }

    float o[16][4];
#pragma unroll
    for (int i = 0; i < 16; i++)
#pragma unroll
        for (int r = 0; r < 4; r++) o[i][r] = 0.0f;
    float m0 = -1e30f, m1 = -1e30f, l0 = 0.0f, l1 = 0.0f;

    for (int kt = 0; kt <= qb; kt++) {
        asm volatile("cp.async.wait_group 0;" ::: "memory");
        __syncthreads();
        if (kt < qb) { fill_kv(kt + 1, (kt + 1) & 1); CP_COMMIT(); }

        const uint32_t kbase = sb + 16384 + (kt & 1) * 32768;
        const uint32_t vbase = kbase + 16384;

        // ---- S = Q @ K^T : warp rows w*16..+15, cols 0..63 (8 n-tiles) ----
        float s[8][4];
#pragma unroll
        for (int nt = 0; nt < 8; nt++) {
#pragma unroll
            for (int r = 0; r < 4; r++) s[nt][r] = 0.0f;
            int krow = nt * 8 + (lane & 7);
            uint32_t krb = kbase + krow * 256;
#pragma unroll
            for (int j2 = 0; j2 < 4; j2++) {
                unsigned kb0, kb1, kb2, kb3;
                int chunk = 4 * j2 + (lane >> 3);
                LDSM4(kb0, kb1, kb2, kb3, krb + ((chunk ^ (krow & 7)) << 4));
                unsigned bfa[2] = {kb0, kb1}, bfb[2] = {kb2, kb3};
                MMA_F16(s[nt], qf[2 * j2],     bfa);
                MMA_F16(s[nt], qf[2 * j2 + 1], bfb);
            }
        }

        // ---- online softmax (rows grp, grp+8; reduce across quad) ----
        float mx0 = -1e30f, mx1 = -1e30f;
#pragma unroll
        for (int nt = 0; nt < 8; nt++) {
#pragma unroll
            for (int r = 0; r < 4; r++) s[nt][r] *= SCALE;
            if (kt == qb) {
                int ct = nt * 8 + tig * 2;
                int rt = w * 16 + grp;
                if (ct     > rt)     s[nt][0] = -1e30f;
                if (ct + 1 > rt)     s[nt][1] = -1e30f;
                if (ct     > rt + 8) s[nt][2] = -1e30f;
                if (ct + 1 > rt + 8) s[nt][3] = -1e30f;
            }
            mx0 = fmaxf(mx0, fmaxf(s[nt][0], s[nt][1]));
            mx1 = fmaxf(mx1, fmaxf(s[nt][2], s[nt][3]));
        }
        mx0 = fmaxf(mx0, __shfl_xor_sync(0xffffffffu, mx0, 1));
        mx0 = fmaxf(mx0, __shfl_xor_sync(0xffffffffu, mx0, 2));
        mx1 = fmaxf(mx1, __shfl_xor_sync(0xffffffffu, mx1, 1));
        mx1 = fmaxf(mx1, __shfl_xor_sync(0xffffffffu, mx1, 2));

        float mn0 = fmaxf(m0, mx0), mn1 = fmaxf(m1, mx1);
        float al0 = __expf(m0 - mn0), al1 = __expf(m1 - mn1);
        float ps0 = 0.0f, ps1 = 0.0f;
        unsigned ph[8][2];
#pragma unroll
        for (int nt = 0; nt < 8; nt++) {
            float e0 = __expf(s[nt][0] - mn0), e1 = __expf(s[nt][1] - mn0);
            float e2 = __expf(s[nt][2] - mn1), e3 = __expf(s[nt][3] - mn1);
            ps0 += e0 + e1; ps1 += e2 + e3;
            __half2 h0 = __floats2half2_rn(e0, e1);
            __half2 h1 = __floats2half2_rn(e2, e3);
            ph[nt][0] = *(unsigned*)&h0;
            ph[nt][1] = *(unsigned*)&h1;
        }
        ps0 += __shfl_xor_sync(0xffffffffu, ps0, 1);
        ps0 += __shfl_xor_sync(0xffffffffu, ps0, 2);
        ps1 += __shfl_xor_sync(0xffffffffu, ps1, 1);
        ps1 += __shfl_xor_sync(0xffffffffu, ps1, 2);
        l0 = l0 * al0 + ps0;  m0 = mn0;
        l1 = l1 * al1 + ps1;  m1 = mn1;
#pragma unroll
        for (int i = 0; i < 16; i++) {
            o[i][0] *= al0; o[i][1] *= al0;
            o[i][2] *= al1; o[i][3] *= al1;
        }

        // ---- O += P @ V  (P fragments straight from registers) ----
#pragma unroll
        for (int ks = 0; ks < 4; ks++) {
            unsigned af[4] = { ph[2 * ks][0], ph[2 * ks][1],
                               ph[2 * ks + 1][0], ph[2 * ks + 1][1] };
            int vrow = 16 * ks + (lane & 15);
            uint32_t vrb = vbase + vrow * 256;
#pragma unroll
            for (int p = 0; p < 8; p++) {
                unsigned v0, v1, v2, v3;
                int chunk = 2 * p + (lane >> 4);
                LDSM4T(v0, v1, v2, v3, vrb + ((chunk ^ (vrow & 7)) << 4));
                unsigned bfa[2] = {v0, v1}, bfb[2] = {v2, v3};
                MMA_F16(o[2 * p],     af, bfa);
                MMA_F16(o[2 * p + 1], af, bfb);
            }
        }
    }

    // ---- epilogue: normalize, write half to g_attnh ----
    {
        float inv0 = 1.0f / l0, inv1 = 1.0f / l1;
        int row0 = qb * 64 + w * 16 + grp;
        size_t t0 = (size_t)(b * S_LEN + row0) * OUT_N + h * HD;
        size_t t1 = t0 + 8 * OUT_N;
#pragma unroll
        for (int i = 0; i < 16; i++) {
            int d = i * 8 + tig * 2;
            __half2 h0 = __floats2half2_rn(o[i][0] * inv0, o[i][1] * inv0);
            __half2 h1 = __floats2half2_rn(o[i][2] * inv1, o[i][3] * inv1);
            *(unsigned*)&g_attnh[t0 + d] = *(unsigned*)&h0;
            *(unsigned*)&g_attnh[t1 + d] = *(unsigned*)&h1;
        }
    }
}

// ---------------- launch ----------------
extern "C" void kernel_launch(void* const* d_in, const int* in_sizes, int n_in,
                              void* d_out, int out_size)
{
    const int*   positions = nullptr;
    const float* hidden = nullptr;
    const float* Wqkv = nullptr;
    const float* bqkv = nullptr;
    const float* Wo = nullptr;
    for (int i = 0; i < n_in; i++) {
        switch (in_sizes[i]) {
            case NTOK:          positions = (const int*)d_in[i]; break;
            case NTOK * HID_D:  hidden = (const float*)d_in[i]; break;
            case HID_D * QKV_N: Wqkv = (const float*)d_in[i]; break;
            case QKV_N:         bqkv = (const float*)d_in[i]; break;
            case OUT_N * HID_D: Wo = (const float*)d_in[i]; break;
        }
    }

    float*  qkv;      cudaGetSymbolAddress((void**)&qkv,      g_qkv);
    __half* hidden_h; cudaGetSymbolAddress((void**)&hidden_h, g_hidden_h);
    __half* wqkvT_h;  cudaGetSymbolAddress((void**)&wqkvT_h,  g_wqkvT_h);
    __half* woT_h;    cudaGetSymbolAddress((void**)&woT_h,    g_woT_h);
    __half* attnh;    cudaGetSymbolAddress((void**)&attnh,    g_attnh);
    float* out = (float*)d_out;

    cudaFuncSetAttribute(gemm_h_kernel<true>,
                         cudaFuncAttributeMaxDynamicSharedMemorySize, GSMEM);
    cudaFuncSetAttribute(gemm_h_kernel<false>,
                         cudaFuncAttributeMaxDynamicSharedMemorySize, GSMEM);
    cudaFuncSetAttribute(flash_mma_kernel,
                         cudaFuncAttributeMaxDynamicSharedMemorySize, FSMEM);

    // 0. RoPE table + operand conversion
    rope_table_kernel<<<(S_LEN * 64 + 255) / 256, 256>>>();
    f2h_kernel<<<(NTOK * HID_D / 4 + 255) / 256, 256>>>(hidden, hidden_h, NTOK * HID_D / 4);
    {
        dim3 blk(32, 8);
        transpose_h_kernel<<<dim3(QKV_N / 32, HID_D / 32), blk>>>(Wqkv, wqkvT_h, HID_D, QKV_N);
        transpose_h_kernel<<<dim3(HID_D / 32, OUT_N / 32), blk>>>(Wo, woT_h, OUT_N, HID_D);
    }

    // 1. QKV projection (+bias)
    {
        dim3 grid(QKV_N / 128, NTOK / 128);
        gemm_h_kernel<true><<<grid, 256, GSMEM>>>(hidden_h, wqkvT_h, bqkv, qkv,
                                                  NTOK, QKV_N, HID_D);
    }

    // 2. RoPE + per-head half layout
    {
        size_t total = (size_t)NTOK * 20 * 64;
        rope_h_kernel<<<(unsigned)((total + 255) / 256), 256>>>(positions);
    }

    // 3. Tensor-core flash attention (writes half output)
    {
        dim3 grid(S_LEN / 64, BATCH * NH);
        flash_mma_kernel<<<grid, 128, FSMEM>>>();
    }

    // 4. Output projection
    {
        dim3 grid(HID_D / 128, NTOK / 128);
        gemm_h_kernel<false><<<grid, 256, GSMEM>>>(attnh, woT_h, nullptr, out,
                                                   NTOK, HID_D, OUT_N);
    }
}

// round 12
// speedup vs baseline: 5.6255x; 1.1857x over previous
#include <cuda_runtime.h>
#include <cuda_fp16.h>
#include <cstdint>
#include <math.h>

#define BATCH  2
#define S_LEN  2048
#define HID_D  2048
#define NH     16
#define NKV    2
#define HD     128
#define QKV_N  ((NH + 2*NKV) * HD)   // 2560
#define NTOK   (BATCH * S_LEN)       // 4096
#define OUT_N  (NH * HD)             // 2048
#define SCALE  0.08838834764831843f  // 128^-0.5

// ---------------- scratch (device globals; no allocation allowed) ----------------
__device__ __align__(16) float  g_qkv[(size_t)NTOK * QKV_N];       // fp32 GEMM1 out
__device__ __align__(16) float  g_cs[(size_t)S_LEN * HD];
__device__ __align__(16) __half g_hidden_h[(size_t)NTOK * HID_D];
__device__ __align__(16) __half g_wqkvT_h[(size_t)QKV_N * HID_D];
__device__ __align__(16) __half g_woT_h[(size_t)HID_D * OUT_N];
__device__ __align__(16) __half g_attnh[(size_t)NTOK * OUT_N];
__device__ __align__(16) __half g_qh[(size_t)BATCH * NH * S_LEN * HD];   // roped Q, per-head
__device__ __align__(16) __half g_kh[(size_t)BATCH * NKV * S_LEN * HD];  // roped K, per-head
__device__ __align__(16) __half g_vh[(size_t)BATCH * NKV * S_LEN * HD];  // V, per-head

// ---------------- common PTX helpers ----------------
__device__ __forceinline__ uint32_t smem_u32(const void* p) {
    uint32_t a;
    asm("{ .reg .u64 t; cvta.to.shared.u64 t, %1; cvt.u32.u64 %0, t; }" : "=r"(a) : "l"(p));
    return a;
}
#define CP16(d, s) \
    asm volatile("cp.async.cg.shared.global [%0], [%1], 16;" :: "r"(d), "l"(s))
#define CP_COMMIT() asm volatile("cp.async.commit_group;" ::: "memory")
#define LDSM4(r0, r1, r2, r3, a)                                              \
    asm volatile("ldmatrix.sync.aligned.m8n8.x4.shared.b16 {%0,%1,%2,%3}, [%4];" \
                 : "=r"(r0), "=r"(r1), "=r"(r2), "=r"(r3) : "r"(a))
#define LDSM4T(r0, r1, r2, r3, a)                                             \
    asm volatile("ldmatrix.sync.aligned.m8n8.x4.trans.shared.b16 {%0,%1,%2,%3}, [%4];" \
                 : "=r"(r0), "=r"(r1), "=r"(r2), "=r"(r3) : "r"(a))
#define MMA_F16(d, a, b)                                                      \
    asm volatile("mma.sync.aligned.m16n8k16.row.col.f32.f16.f16.f32 "         \
                 "{%0,%1,%2,%3}, {%4,%5,%6,%7}, {%8,%9}, {%0,%1,%2,%3};"      \
                 : "+f"(d[0]), "+f"(d[1]), "+f"(d[2]), "+f"(d[3])             \
                 : "r"(a[0]), "r"(a[1]), "r"(a[2]), "r"(a[3]),                \
                   "r"(b[0]), "r"(b[1]))

// ---------------- RoPE cos/sin table (fp64 for angle accuracy) ----------------
__global__ void rope_table_kernel() {
    int idx = blockIdx.x * blockDim.x + threadIdx.x;
    if (idx >= S_LEN * 64) return;
    int s = idx >> 6, i = idx & 63;
    double inv = pow(1000000.0, -(double)i / 64.0);
    double ang = (double)s * inv;
    g_cs[s * HD + i]      = (float)cos(ang);
    g_cs[s * HD + 64 + i] = (float)sin(ang);
}

// ------- RoPE + convert to per-head half layout (q 16h, k 2h rope; v 2h copy) -------
__global__ void rope_h_kernel(const int* __restrict__ positions) {
    size_t idx = (size_t)blockIdx.x * blockDim.x + threadIdx.x;
    const size_t total = (size_t)NTOK * 20 * 64;   // 18 rope heads + 2 v heads
    if (idx >= total) return;
    int i    = idx & 63;
    size_t r = idx >> 6;
    int head = (int)(r % 20);
    int t    = (int)(r / 20);
    int b = t / S_LEN, s = t % S_LEN;
    int pos  = positions[t];
    if (head < NH + NKV) {
        float c  = g_cs[pos * HD + i];
        float sn = g_cs[pos * HD + 64 + i];
        const float* p;
        __half* out;
        if (head < NH) {
            p   = g_qkv + (size_t)t * QKV_N + head * HD;
            out = g_qh + ((size_t)(b * NH + head) * S_LEN + s) * HD;
        } else {
            int kvh = head - NH;
            p   = g_qkv + (size_t)t * QKV_N + NH * HD + kvh * HD;
            out = g_kh + ((size_t)(b * NKV + kvh) * S_LEN + s) * HD;
        }
        float x1 = p[i], x2 = p[i + 64];
        out[i]      = __float2half(x1 * c - x2 * sn);
        out[i + 64] = __float2half(x2 * c + x1 * sn);
    } else {
        int kvh = head - NH - NKV;
        const float* p = g_qkv + (size_t)t * QKV_N + (NH + NKV) * HD + kvh * HD;
        __half* out = g_vh + ((size_t)(b * NKV + kvh) * S_LEN + s) * HD;
        out[i]      = __float2half(p[i]);
        out[i + 64] = __float2half(p[i + 64]);
    }
}

// ---------------- fp32 -> fp16 convert ----------------
__global__ void f2h_kernel(const float* __restrict__ in, __half* __restrict__ out, int n4) {
    int i = blockIdx.x * blockDim.x + threadIdx.x;
    if (i >= n4) return;
    float4 v = ((const float4*)in)[i];
    __half2 h0 = __floats2half2_rn(v.x, v.y);
    __half2 h1 = __floats2half2_rn(v.z, v.w);
    ((uint2*)out)[i] = make_uint2(*(unsigned*)&h0, *(unsigned*)&h1);
}

// ---------------- weight transpose + convert: out_h[N][K] = in[K][N] ----------------
__global__ void transpose_h_kernel(const float* __restrict__ in, __half* __restrict__ out,
                                   int rows, int cols) {
    __shared__ float t[32][33];
    int x = blockIdx.x * 32 + threadIdx.x;
    int y = blockIdx.y * 32 + threadIdx.y;
#pragma unroll
    for (int j = 0; j < 32; j += 8)
        t[threadIdx.y + j][threadIdx.x] = in[(size_t)(y + j) * cols + x];
    __syncthreads();
    x = blockIdx.y * 32 + threadIdx.x;
    y = blockIdx.x * 32 + threadIdx.y;
#pragma unroll
    for (int j = 0; j < 32; j += 8)
        out[(size_t)(y + j) * rows + x] = __float2half(t[threadIdx.x][threadIdx.y + j]);
}

// ============ fp16 mma GEMM, cp.async 4-stage + ldmatrix ============
#define GSTAGE  16384
#define GSMEM   (4 * GSTAGE)

template <bool BIAS>
__global__ __launch_bounds__(256, 2) void gemm_h_kernel(
    const __half* __restrict__ A, const __half* __restrict__ Bt,
    const float* __restrict__ bias, float* __restrict__ C,
    int M, int N, int K)
{
    extern __shared__ char gsm[];
    const uint32_t sb = smem_u32(gsm);
    const int tid = threadIdx.x;
    const int lane = tid & 31, w = tid >> 5;
    const int bm = blockIdx.y * 128, bn = blockIdx.x * 128;
    const int wm = (w >> 2) * 64, wn = (w & 3) * 32;
    const int grp = lane >> 2, tig = lane & 3;

    const int fr = tid >> 1;
    const int fc0 = (tid & 1) * 2;
    const __half* Ap = A  + (size_t)(bm + fr) * K + fc0 * 8;
    const __half* Bp = Bt + (size_t)(bn + fr) * K + fc0 * 8;
    const uint32_t fsw0 = (uint32_t)(fr * 64 + (((fc0 + 0) ^ ((fr >> 1) & 3)) << 4));
    const uint32_t fsw1 = (uint32_t)(fr * 64 + (((fc0 + 1) ^ ((fr >> 1) & 3)) << 4));

    uint32_t a_off[4][2], b_off[2][2];
    {
        const int j = lane >> 3, lr = lane & 7;
#pragma unroll
        for (int mt = 0; mt < 4; mt++)
#pragma unroll
            for (int ks = 0; ks < 2; ks++) {
                int row = wm + mt * 16 + (j & 1) * 8 + lr;
                int kc  = ks * 2 + (j >> 1);
                a_off[mt][ks] = (uint32_t)(row * 64 + ((kc ^ ((row >> 1) & 3)) << 4));
            }
#pragma unroll
        for (int np = 0; np < 2; np++)
#pragma unroll
            for (int ks = 0; ks < 2; ks++) {
                int nt  = np * 2 + (j >> 1);
                int row = wn + nt * 8 + lr;
                int kc  = ks * 2 + (j & 1);
                b_off[np][ks] = (uint32_t)(8192 + row * 64 + ((kc ^ ((row >> 1) & 3)) << 4));
            }
    }

    float acc[4][4][4];
#pragma unroll
    for (int mt = 0; mt < 4; mt++)
#pragma unroll
        for (int nt = 0; nt < 4; nt++)
#pragma unroll
            for (int r = 0; r < 4; r++) acc[mt][nt][r] = 0.0f;

    const int nk = K >> 5;

    auto load_stage = [&](int kt, int st) {
        uint32_t s = sb + st * GSTAGE;
        const __half* ap = Ap + kt * 32;
        const __half* bp = Bp + kt * 32;
        CP16(s + fsw0,        ap);
        CP16(s + fsw1,        ap + 8);
        CP16(s + 8192 + fsw0, bp);
        CP16(s + 8192 + fsw1, bp + 8);
    };

#pragma unroll
    for (int s = 0; s < 3; s++) { load_stage(s, s); CP_COMMIT(); }

    for (int kt = 0; kt < nk; kt++) {
        asm volatile("cp.async.wait_group 2;" ::: "memory");
        __syncthreads();
        const int st = kt & 3;
        if (kt + 3 < nk) load_stage(kt + 3, (kt + 3) & 3);
        CP_COMMIT();

        const uint32_t s = sb + st * GSTAGE;
#pragma unroll
        for (int ks = 0; ks < 2; ks++) {
            unsigned af[4][4], bf[4][2];
#pragma unroll
            for (int mt = 0; mt < 4; mt++)
                LDSM4(af[mt][0], af[mt][1], af[mt][2], af[mt][3], s + a_off[mt][ks]);
#pragma unroll
            for (int np = 0; np < 2; np++)
                LDSM4(bf[np * 2][0], bf[np * 2][1], bf[np * 2 + 1][0], bf[np * 2 + 1][1],
                      s + b_off[np][ks]);
#pragma unroll
            for (int mt = 0; mt < 4; mt++)
#pragma unroll
                for (int nt = 0; nt < 4; nt++)
                    MMA_F16(acc[mt][nt], af[mt], bf[nt]);
        }
    }

#pragma unroll
    for (int nt = 0; nt < 4; nt++) {
        int c = bn + wn + nt * 8 + tig * 2;
        float b0 = 0.0f, b1 = 0.0f;
        if (BIAS) { b0 = bias[c]; b1 = bias[c + 1]; }
#pragma unroll
        for (int mt = 0; mt < 4; mt++) {
            int r = bm + wm + mt * 16 + grp;
            float2 v0, v1;
            v0.x = acc[mt][nt][0] + b0; v0.y = acc[mt][nt][1] + b1;
            v1.x = acc[mt][nt][2] + b0; v1.y = acc[mt][nt][3] + b1;
            *(float2*)&C[(size_t)r * N + c]       = v0;
            *(float2*)&C[(size_t)(r + 8) * N + c] = v1;
        }
    }
}

// ============ Tensor-core flash attention: BQ=128, BK=64, 8 warps ============
// smem: Q 32KB @0 | stage0: K@32768 V@49152 | stage1: K@65536 V@81920  (96KB)
// Row = 128 halfs = 256B = 16 chunks of 16B; chunk c of row r at (c ^ (r&7)).
#define FSMEM 98304

__global__ __launch_bounds__(256) void flash_mma_kernel()
{
    extern __shared__ char fsm[];
    const uint32_t sb = smem_u32(fsm);
    const int tid = threadIdx.x, lane = tid & 31, w = tid >> 5;
    const int grp = lane >> 2, tig = lane & 3;
    const int qb = blockIdx.x, bh = blockIdx.y;
    const int b = bh >> 4, h = bh & 15, kvh = h >> 3;

    const __half* qptr = g_qh + ((size_t)(b * NH + h) * S_LEN + qb * 128) * HD;
    const __half* kptr = g_kh + (size_t)(b * NKV + kvh) * S_LEN * HD;
    const __half* vptr = g_vh + (size_t)(b * NKV + kvh) * S_LEN * HD;

    // ---- prologue: async-load Q tile (128 rows, 256 threads: half row each) ----
    {
        const int fr = tid >> 1, fc0 = (tid & 1) * 8;
        const __half* src = qptr + (size_t)fr * HD + fc0 * 8;
        uint32_t dst = sb + fr * 256;
#pragma unroll
        for (int j = 0; j < 8; j++) {
            int c = fc0 + j;
            CP16(dst + ((c ^ (fr & 7)) << 4), src + j * 8);
        }
    }
    CP_COMMIT();

    // KV fill: 64 rows, 256 threads -> quarter row each (4 chunks K + 4 chunks V)
    const int kfr = tid >> 2, kfc0 = (tid & 3) * 4;
    auto fill_kv = [&](int kt, int st) {
        uint32_t kb = sb + 32768 + st * 32768;
        const __half* ks = kptr + (size_t)(kt * 64 + kfr) * HD + kfc0 * 8;
        const __half* vs = vptr + (size_t)(kt * 64 + kfr) * HD + kfc0 * 8;
        uint32_t rb = kfr * 256;
#pragma unroll
        for (int j = 0; j < 4; j++) {
            int c = kfc0 + j;
            uint32_t sw = rb + ((c ^ (kfr & 7)) << 4);
            CP16(kb + sw,         ks + j * 8);
            CP16(kb + 16384 + sw, vs + j * 8);
        }
    };
    fill_kv(0, 0);
    CP_COMMIT();

    // ---- Q fragments into registers (warp rows w*16..+15, kept whole loop) ----
    asm volatile("cp.async.wait_group 1;" ::: "memory");
    __syncthreads();
    unsigned qf[8][4];
    {
        int row = w * 16 + ((lane >> 3) & 1) * 8 + (lane & 7);
        uint32_t rb = sb + row * 256;
#pragma unroll
        for (int j = 0; j < 8; j++) {
            int chunk = 2 * j + (lane >> 4);
            LDSM4(qf[j][0], qf[j][1], qf[j][2], qf[j][3],
                  rb + ((chunk ^ (row & 7)) << 4));
        }
    }

    float o[16][4];
#pragma unroll
    for (int i = 0; i < 16; i++)
#pragma unroll
        for (int r = 0; r < 4; r++) o[i][r] = 0.0f;
    float m0 = -1e30f, m1 = -1e30f, l0 = 0.0f, l1 = 0.0f;

    const int ktmax = 2 * qb + 1;
    for (int kt = 0; kt <= ktmax; kt++) {
        asm volatile("cp.async.wait_group 0;" ::: "memory");
        __syncthreads();
        if (kt < ktmax) { fill_kv(kt + 1, (kt + 1) & 1); CP_COMMIT(); }

        const uint32_t kbase = sb + 32768 + (kt & 1) * 32768;
        const uint32_t vbase = kbase + 16384;

        // ---- S = Q @ K^T : warp rows w*16..+15, cols 0..63 (8 n-tiles) ----
        float s[8][4];
#pragma unroll
        for (int nt = 0; nt < 8; nt++) {
#pragma unroll
            for (int r = 0; r < 4; r++) s[nt][r] = 0.0f;
            int krow = nt * 8 + (lane & 7);
            uint32_t krb = kbase + krow * 256;
#pragma unroll
            for (int j2 = 0; j2 < 4; j2++) {
                unsigned kb0, kb1, kb2, kb3;
                int chunk = 4 * j2 + (lane >> 3);
                LDSM4(kb0, kb1, kb2, kb3, krb + ((chunk ^ (krow & 7)) << 4));
                unsigned bfa[2] = {kb0, kb1}, bfb[2] = {kb2, kb3};
                MMA_F16(s[nt], qf[2 * j2],     bfa);
                MMA_F16(s[nt], qf[2 * j2 + 1], bfb);
            }
        }

        // ---- online softmax (rows grp, grp+8 of warp tile; quad reduce) ----
        float mx0 = -1e30f, mx1 = -1e30f;
        const bool need_mask = (kt >= 2 * qb);
        const int rt0 = qb * 128 + w * 16 + grp;
#pragma unroll
        for (int nt = 0; nt < 8; nt++) {
#pragma unroll
            for (int r = 0; r < 4; r++) s[nt][r] *= SCALE;
            if (need_mask) {
                int ct = kt * 64 + nt * 8 + tig * 2;
                if (ct     > rt0)     s[nt][0] = -1e30f;
                if (ct + 1 > rt0)     s[nt][1] = -1e30f;
                if (ct     > rt0 + 8) s[nt][2] = -1e30f;
                if (ct + 1 > rt0 + 8) s[nt][3] = -1e30f;
            }
            mx0 = fmaxf(mx0, fmaxf(s[nt][0], s[nt][1]));
            mx1 = fmaxf(mx1, fmaxf(s[nt][2], s[nt][3]));
        }
        mx0 = fmaxf(mx0, __shfl_xor_sync(0xffffffffu, mx0, 1));
        mx0 = fmaxf(mx0, __shfl_xor_sync(0xffffffffu, mx0, 2));
        mx1 = fmaxf(mx1, __shfl_xor_sync(0xffffffffu, mx1, 1));
        mx1 = fmaxf(mx1, __shfl_xor_sync(0xffffffffu, mx1, 2));

        float mn0 = fmaxf(m0, mx0), mn1 = fmaxf(m1, mx1);
        float al0 = __expf(m0 - mn0), al1 = __expf(m1 - mn1);
        float ps0 = 0.0f, ps1 = 0.0f;
        unsigned ph[8][2];
#pragma unroll
        for (int nt = 0; nt < 8; nt++) {
            float e0 = __expf(s[nt][0] - mn0), e1 = __expf(s[nt][1] - mn0);
            float e2 = __expf(s[nt][2] - mn1), e3 = __expf(s[nt][3] - mn1);
            ps0 += e0 + e1; ps1 += e2 + e3;
            __half2 h0 = __floats2half2_rn(e0, e1);
            __half2 h1 = __floats2half2_rn(e2, e3);
            ph[nt][0] = *(unsigned*)&h0;
            ph[nt][1] = *(unsigned*)&h1;
        }
        ps0 += __shfl_xor_sync(0xffffffffu, ps0, 1);
        ps0 += __shfl_xor_sync(0xffffffffu, ps0, 2);
        ps1 += __shfl_xor_sync(0xffffffffu, ps1, 1);
        ps1 += __shfl_xor_sync(0xffffffffu, ps1, 2);
        l0 = l0 * al0 + ps0;  m0 = mn0;
        l1 = l1 * al1 + ps1;  m1 = mn1;
#pragma unroll
        for (int i = 0; i < 16; i++) {
            o[i][0] *= al0; o[i][1] *= al0;
            o[i][2] *= al1; o[i][3] *= al1;
        }

        // ---- O += P @ V  (P fragments straight from registers) ----
#pragma unroll
        for (int ks = 0; ks < 4; ks++) {
            unsigned af[4] = { ph[2 * ks][0], ph[2 * ks][1],
                               ph[2 * ks + 1][0], ph[2 * ks + 1][1] };
            int vrow = 16 * ks + (lane & 15);
            uint32_t vrb = vbase + vrow * 256;
#pragma unroll
            for (int p = 0; p < 8; p++) {
                unsigned v0, v1, v2, v3;
                int chunk = 2 * p + (lane >> 4);
                LDSM4T(v0, v1, v2, v3, vrb + ((chunk ^ (vrow & 7)) << 4));
                unsigned bfa[2] = {v0, v1}, bfb[2] = {v2, v3};
                MMA_F16(o[2 * p],     af, bfa);
                MMA_F16(o[2 * p + 1], af, bfb);
            }
        }
    }

    // ---- epilogue: normalize, write half to g_attnh ----
    {
        float inv0 = 1.0f / l0, inv1 = 1.0f / l1;
        int row0 = qb * 128 + w * 16 + grp;
        size_t t0 = (size_t)(b * S_LEN + row0) * OUT_N + h * HD;
        size_t t1 = t0 + 8 * OUT_N;
#pragma unroll
        for (int i = 0; i < 16; i++) {
            int d = i * 8 + tig * 2;
            __half2 h0 = __floats2half2_rn(o[i][0] * inv0, o[i][1] * inv0);
            __half2 h1 = __floats2half2_rn(o[i][2] * inv1, o[i][3] * inv1);
            *(unsigned*)&g_attnh[t0 + d] = *(unsigned*)&h0;
            *(unsigned*)&g_attnh[t1 + d] = *(unsigned*)&h1;
        }
    }
}

// ---------------- launch ----------------
extern "C" void kernel_launch(void* const* d_in, const int* in_sizes, int n_in,
                              void* d_out, int out_size)
{
    const int*   positions = nullptr;
    const float* hidden = nullptr;
    const float* Wqkv = nullptr;
    const float* bqkv = nullptr;
    const float* Wo = nullptr;
    for (int i = 0; i < n_in; i++) {
        switch (in_sizes[i]) {
            case NTOK:          positions = (const int*)d_in[i]; break;
            case NTOK * HID_D:  hidden = (const float*)d_in[i]; break;
            case HID_D * QKV_N: Wqkv = (const float*)d_in[i]; break;
            case QKV_N:         bqkv = (const float*)d_in[i]; break;
            case OUT_N * HID_D: Wo = (const float*)d_in[i]; break;
        }
    }

    float*  qkv;      cudaGetSymbolAddress((void**)&qkv,      g_qkv);
    __half* hidden_h; cudaGetSymbolAddress((void**)&hidden_h, g_hidden_h);
    __half* wqkvT_h;  cudaGetSymbolAddress((void**)&wqkvT_h,  g_wqkvT_h);
    __half* woT_h;    cudaGetSymbolAddress((void**)&woT_h,    g_woT_h);
    __half* attnh;    cudaGetSymbolAddress((void**)&attnh,    g_attnh);
    float* out = (float*)d_out;

    cudaFuncSetAttribute(gemm_h_kernel<true>,
                         cudaFuncAttributeMaxDynamicSharedMemorySize, GSMEM);
    cudaFuncSetAttribute(gemm_h_kernel<false>,
                         cudaFuncAttributeMaxDynamicSharedMemorySize, GSMEM);
    cudaFuncSetAttribute(flash_mma_kernel,
                         cudaFuncAttributeMaxDynamicSharedMemorySize, FSMEM);

    // 0. RoPE table + operand conversion
    rope_table_kernel<<<(S_LEN * 64 + 255) / 256, 256>>>();
    f2h_kernel<<<(NTOK * HID_D / 4 + 255) / 256, 256>>>(hidden, hidden_h, NTOK * HID_D / 4);
    {
        dim3 blk(32, 8);
        transpose_h_kernel<<<dim3(QKV_N / 32, HID_D / 32), blk>>>(Wqkv, wqkvT_h, HID_D, QKV_N);
        transpose_h_kernel<<<dim3(HID_D / 32, OUT_N / 32), blk>>>(Wo, woT_h, OUT_N, HID_D);
    }

    // 1. QKV projection (+bias)
    {
        dim3 grid(QKV_N / 128, NTOK / 128);
        gemm_h_kernel<true><<<grid, 256, GSMEM>>>(hidden_h, wqkvT_h, bqkv, qkv,
                                                  NTOK, QKV_N, HID_D);
    }

    // 2. RoPE + per-head half layout
    {
        size_t total = (size_t)NTOK * 20 * 64;
        rope_h_kernel<<<(unsigned)((total + 255) / 256), 256>>>(positions);
    }

    // 3. Tensor-core flash attention (BQ=128, writes half output)
    {
        dim3 grid(S_LEN / 128, BATCH * NH);
        flash_mma_kernel<<<grid, 256, FSMEM>>>();
    }

    // 4. Output projection
    {
        dim3 grid(HID_D / 128, NTOK / 128);
        gemm_h_kernel<false><<<grid, 256, GSMEM>>>(attnh, woT_h, nullptr, out,
                                                   NTOK, HID_D, OUT_N);
    }
}